// round 10
// baseline (speedup 1.0000x reference)
#include <cuda_runtime.h>
#include <cuda_bf16.h>
#include <cstdint>

#define BB 8
#define CC 128
#define TT 128
#define FF 512
#define KK 64
#define S_SIDE (TT*FF)
#define S_LAT  (TT*KK)

typedef unsigned long long u64;
typedef unsigned int u32;
typedef unsigned short u16;

// ---------------- scratch ----------------
__device__ float g_buf1[BB*CC*S_SIDE];            // attention out
__device__ float g_buf2[BB*CC*S_SIDE];            // q (fp32)
__device__ float g_buf3[BB*CC*S_SIDE];            // query_h (fp32, for skip)
__device__ float g_rms [BB*S_SIDE];               // side/ffn inv-rms
__device__ float g_rmsL[BB*S_LAT];                // latent inv-rms (separate! no aliasing)
__device__ float g_k  [BB*CC*S_LAT];
__device__ float g_v  [BB*CC*S_LAT];

// bf16 hi/lo tile buffers: per (b,tile): 16384 hi + 16384 lo u16
__device__ u16 g_tA[8*512*32768];                 // glu1 out / glu2 out
__device__ u16 g_tB[8*512*32768];                 // qmlp_out out
__device__ u16 g_tL[8*64*32768];                  // latent_h

// pre-converted weights (hi block then lo block per matrix)
#define WLP 0
#define WK  32768
#define WV  65536
#define WQO 98304
#define WQ  131072
#define WO  163840
#define WFO 196608
#define WQI 229376
#define WFI 294912
__device__ u16 g_wbf[360448];

__device__ __forceinline__ float silu_f(float x) { return x / (1.0f + __expf(-x)); }
__device__ __forceinline__ u64 dup2(float v) {
    u64 r; asm("mov.b64 %0, {%1, %2};" : "=l"(r) : "f"(v), "f"(v)); return r;
}
__device__ __forceinline__ void fma2(u64& d, u64 a, u64 b) {
    asm("fma.rn.f32x2 %0, %1, %2, %0;" : "+l"(d) : "l"(a), "l"(b));
}
__device__ __forceinline__ float2 unpack2(u64 v) {
    float2 r; asm("mov.b64 {%0, %1}, %2;" : "=f"(r.x), "=f"(r.y) : "l"(v)); return r;
}
__device__ __forceinline__ u32 smem_u32(const void* p) {
    u32 a;
    asm("{ .reg .u64 t; cvta.to.shared.u64 t, %1; cvt.u32.u64 %0, t; }" : "=r"(a) : "l"(p));
    return a;
}

// ---------------- mma.sync helpers ----------------
__device__ __forceinline__ void ldsm4(u32* r, u32 addr) {
    asm volatile("ldmatrix.sync.aligned.m8n8.x4.shared.b16 {%0,%1,%2,%3}, [%4];"
                 : "=r"(r[0]), "=r"(r[1]), "=r"(r[2]), "=r"(r[3]) : "r"(addr));
}
__device__ __forceinline__ void mma16816(float* d, const u32* a, const u32* b) {
    asm volatile("mma.sync.aligned.m16n8k16.row.col.f32.bf16.bf16.f32 "
                 "{%0,%1,%2,%3}, {%4,%5,%6,%7}, {%8,%9}, {%0,%1,%2,%3};"
                 : "+f"(d[0]), "+f"(d[1]), "+f"(d[2]), "+f"(d[3])
                 : "r"(a[0]), "r"(a[1]), "r"(a[2]), "r"(a[3]), "r"(b[0]), "r"(b[1]));
}
__device__ __forceinline__ void cpa16(u32 saddr, const void* g) {
    asm volatile("cp.async.cg.shared.global [%0], [%1], 16;" :: "r"(saddr), "l"(g));
}
#define CP_COMMIT() asm volatile("cp.async.commit_group;" ::: "memory")
#define CP_WAIT0()  asm volatile("cp.async.wait_group 0;" ::: "memory")
#define CP_WAIT1()  asm volatile("cp.async.wait_group 1;" ::: "memory")

#define TSTR  272
#define TILE_B (128*TSTR)
#define TP 132

// fp32 -> bf16 hi/lo split, store 4 cols to padded smem tiles
__device__ __forceinline__ void cvt_store4(char* smem, u32 hi_base, u32 lo_base,
                                           int row, int col, float4 x) {
    __nv_bfloat16 h0 = __float2bfloat16_rn(x.x); float r0 = x.x - __bfloat162float(h0);
    __nv_bfloat16 h1 = __float2bfloat16_rn(x.y); float r1 = x.y - __bfloat162float(h1);
    __nv_bfloat16 h2 = __float2bfloat16_rn(x.z); float r2 = x.z - __bfloat162float(h2);
    __nv_bfloat16 h3 = __float2bfloat16_rn(x.w); float r3 = x.w - __bfloat162float(h3);
    __nv_bfloat16 l0 = __float2bfloat16_rn(r0);
    __nv_bfloat16 l1 = __float2bfloat16_rn(r1);
    __nv_bfloat16 l2 = __float2bfloat16_rn(r2);
    __nv_bfloat16 l3 = __float2bfloat16_rn(r3);
    u64 hv = (u64)*(u16*)&h0 | ((u64)*(u16*)&h1 << 16) | ((u64)*(u16*)&h2 << 32) | ((u64)*(u16*)&h3 << 48);
    u64 lv = (u64)*(u16*)&l0 | ((u64)*(u16*)&l1 << 16) | ((u64)*(u16*)&l2 << 32) | ((u64)*(u16*)&l3 << 48);
    u32 o = (u32)(row * TSTR + col * 2);
    *(u64*)(smem + hi_base + o) = hv;
    *(u64*)(smem + lo_base + o) = lv;
}

__device__ __forceinline__ u32 pack_hl(float v) {
    __nv_bfloat16 h = __float2bfloat16_rn(v);
    float l = v - __bfloat162float(h);
    __nv_bfloat16 lo = __float2bfloat16_rn(l);
    return (u32)*(u16*)&h | ((u32)*(u16*)&lo << 16);
}

// stage one contiguous 128x128 u16 tile into TSTR-padded smem via cp.async
__device__ __forceinline__ void stage_tile(u32 sbase, const u16* g, int tid) {
    #pragma unroll
    for (int it = 0; it < 8; it++) {
        int idx = tid + it * 256;
        int r = idx >> 4, ch = idx & 15;
        cpa16(sbase + r * TSTR + ch * 16, g + r * 128 + ch * 8);
    }
}

// one k=128 HMMA pass over a 128x128 tile pair; warp covers 32m x 64n
__device__ __forceinline__ void mm_pass(u32 ab, u32 bb, float (*acc)[8][4],
                                        u32 a_row, u32 a_koff, u32 b_row, u32 b_koff,
                                        int n_blk)
{
    #pragma unroll
    for (int ks = 0; ks < 8; ks++) {
        int k0 = ks * 16;
        u32 af[2][4], bf[4][4];
        #pragma unroll
        for (int i = 0; i < 2; i++)
            ldsm4(af[i], ab + (a_row + i * 16) * TSTR + (k0 + a_koff) * 2);
        #pragma unroll
        for (int j = 0; j < 4; j++)
            ldsm4(bf[j], bb + (n_blk + j * 16 + b_row) * TSTR + (k0 + b_koff) * 2);
        #pragma unroll
        for (int i = 0; i < 2; i++)
            #pragma unroll
            for (int j = 0; j < 8; j++)
                mma16816(acc[i][j], af[i], &bf[j >> 1][(j & 1) * 2]);
    }
}

// ---------------- fused weight pre-convert (gamma folded) ----------------
__global__ __launch_bounds__(256)
void convert_all(const float* __restrict__ lp_w, const float* __restrict__ k_w,
                 const float* __restrict__ v_w,  const float* __restrict__ qo_w,
                 const float* __restrict__ q_w,  const float* __restrict__ o_w,
                 const float* __restrict__ fo_w, const float* __restrict__ qi_w,
                 const float* __restrict__ fi_w, const float* __restrict__ lp_g,
                 const float* __restrict__ qn_g, const float* __restrict__ ffn_g,
                 u16* __restrict__ dst)
{
    int bid = blockIdx.x;
    const float* src; const float* gamma = nullptr; int off, n, lb;
    if (bid < 448) {
        int seg = bid >> 6; lb = bid & 63; n = 16384;
        switch (seg) {
            case 0: src = lp_w; gamma = lp_g; off = WLP; break;
            case 1: src = k_w;  off = WK;  break;
            case 2: src = v_w;  off = WV;  break;
            case 3: src = qo_w; off = WQO; break;
            case 4: src = q_w;  off = WQ;  break;
            case 5: src = o_w;  off = WO;  break;
            default: src = fo_w; off = WFO; break;
        }
    } else if (bid < 576) {
        lb = bid - 448; src = qi_w; gamma = qn_g; off = WQI; n = 32768;
    } else {
        lb = bid - 576; src = fi_w; gamma = ffn_g; off = WFI; n = 32768;
    }
    int idx = lb * 256 + threadIdx.x;
    if (idx >= n) return;
    float v = src[idx];
    if (gamma) v *= gamma[idx & 127];
    __nv_bfloat16 h = __float2bfloat16_rn(v);
    float l = v - __bfloat162float(h);
    __nv_bfloat16 lo = __float2bfloat16_rn(l);
    dst[off + idx] = *(u16*)&h;
    dst[off + n + idx] = *(u16*)&lo;
}

// ---------------- inv-RMS ----------------
__global__ __launch_bounds__(256)
void rms_scale_kernel(const float* __restrict__ X, float* __restrict__ R, int S)
{
    int b = blockIdx.y;
    int s = blockIdx.x * 1024 + threadIdx.x * 4;
    const float* xb = X + (size_t)b * CC * S + s;
    float4 acc = make_float4(0.f, 0.f, 0.f, 0.f);
    #pragma unroll 4
    for (int c = 0; c < CC; c++) {
        float4 v = *(const float4*)(xb + (size_t)c * S);
        acc.x += v.x * v.x; acc.y += v.y * v.y;
        acc.z += v.z * v.z; acc.w += v.w * v.w;
    }
    const float inv = 1.0f / CC;
    float4 r;
    r.x = rsqrtf(acc.x * inv + 1e-6f);
    r.y = rsqrtf(acc.y * inv + 1e-6f);
    r.z = rsqrtf(acc.z * inv + 1e-6f);
    r.w = rsqrtf(acc.w * inv + 1e-6f);
    *(float4*)(R + (size_t)b * S + s) = r;
}

// ================= GEMM smem: 3 buffers (P0=Ahi, P1=Bhi, P2=Blo->Alo) =================
#define P0 0
#define P1 TILE_B
#define P2 (2*TILE_B)
#define GT_SMEM (3*TILE_B)

// ================= GEMM, bf16-tile input =================
template<int EPI, int OUTFMT>
__global__ __launch_bounds__(256, 2)
void gemm_bfin(const u16* __restrict__ wsc, const float* __restrict__ bias,
               const u16* __restrict__ tin, u16* __restrict__ tout,
               float* __restrict__ Y, const float* __restrict__ extra,
               const float* __restrict__ sc_p, int S)
{
    extern __shared__ char sm[];
    u32 sb = smem_u32(sm);
    int tid = threadIdx.x;
    int wid = tid >> 5, lane = tid & 31;
    int b  = blockIdx.y;
    int s0 = blockIdx.x * 128;
    size_t tb = ((size_t)(b * gridDim.x + blockIdx.x)) * 32768;

    stage_tile(sb + P0, wsc, tid);              // Ahi
    stage_tile(sb + P1, tin + tb, tid);         // Bhi
    CP_COMMIT();
    stage_tile(sb + P2, tin + tb + 16384, tid); // Blo
    CP_COMMIT();

    int m_blk = (wid & 3) * 32;
    int n_blk = (wid >> 2) * 64;
    float acc[2][8][4];
    #pragma unroll
    for (int i = 0; i < 2; i++)
        #pragma unroll
        for (int j = 0; j < 8; j++)
            #pragma unroll
            for (int q = 0; q < 4; q++) acc[i][j][q] = 0.f;

    u32 a_row = (u32)(m_blk + (lane & 15));
    u32 a_koff = (u32)((lane >> 4) << 3);
    u32 b_row = (u32)((lane & 7) + ((lane >> 4) << 3));
    u32 b_koff = (u32)(((lane >> 3) & 1) << 3);

    CP_WAIT1(); __syncthreads();
    mm_pass(sb + P0, sb + P1, acc, a_row, a_koff, b_row, b_koff, n_blk);   // Ahi*Bhi
    CP_WAIT0(); __syncthreads();
    mm_pass(sb + P0, sb + P2, acc, a_row, a_koff, b_row, b_koff, n_blk);   // Ahi*Blo
    __syncthreads();
    stage_tile(sb + P2, wsc + 16384, tid);      // Alo
    CP_COMMIT(); CP_WAIT0(); __syncthreads();
    mm_pass(sb + P2, sb + P1, acc, a_row, a_koff, b_row, b_koff, n_blk);   // Alo*Bhi

    float scl = (EPI == 1) ? *sc_p : 0.f;
    u32* trans = (u32*)sm;
    if (OUTFMT >= 1) __syncthreads();
    #pragma unroll
    for (int i = 0; i < 2; i++) {
        #pragma unroll
        for (int j = 0; j < 8; j++) {
            int c = n_blk + j * 8 + (lane & 3) * 2;
            #pragma unroll
            for (int h = 0; h < 2; h++) {
                int o = m_blk + i * 16 + (lane >> 2) + h * 8;
                float bv = bias[o];
                float v0 = acc[i][j][h * 2 + 0] + bv;
                float v1 = acc[i][j][h * 2 + 1] + bv;
                if (OUTFMT != 1) {
                    float* yp = Y + ((size_t)b * CC + o) * S + s0 + c;
                    float w0 = v0, w1 = v1;
                    if (EPI == 1) {
                        const float* ep = extra + ((size_t)b * CC + o) * S + s0 + c;
                        w0 += scl * ep[0]; w1 += scl * ep[1];
                    }
                    if (EPI == 2) { w0 += yp[0]; w1 += yp[1]; }
                    float2 ov; ov.x = w0; ov.y = w1;
                    *(float2*)yp = ov;
                }
                if (OUTFMT >= 1) {
                    trans[c * TP + o] = pack_hl(v0);
                    trans[(c + 1) * TP + o] = pack_hl(v1);
                }
            }
        }
    }
    if (OUTFMT >= 1) {
        __syncthreads();
        u16* thi = tout + tb;
        u16* tlo = thi + 16384;
        #pragma unroll
        for (int it = 0; it < 16; it++) {
            int idx = tid + it * 256;
            int s = idx >> 5, c0 = (idx & 31) * 4;
            uint4 w = *(const uint4*)(trans + s * TP + c0);
            u64 hv = (u64)(w.x & 0xffff) | ((u64)(w.y & 0xffff) << 16)
                   | ((u64)(w.z & 0xffff) << 32) | ((u64)(w.w & 0xffff) << 48);
            u64 lv = (u64)(w.x >> 16) | ((u64)(w.y >> 16) << 16)
                   | ((u64)(w.z >> 16) << 32) | ((u64)(w.w >> 16) << 48);
            *(u64*)(thi + s * 128 + c0) = hv;
            *(u64*)(tlo + s * 128 + c0) = lv;
        }
    }
}

// ================= GEMM, fp32 input =================
template<int NORM, int ACT, int EPI, int OUTFMT>
__global__ __launch_bounds__(256, 2)
void gemm_f32in(const float* __restrict__ X, const u16* __restrict__ wsc,
                const float* __restrict__ bias, float* __restrict__ Y,
                const float* __restrict__ extra, const float* __restrict__ sc_p,
                const float* __restrict__ rms, u16* __restrict__ tout, int S)
{
    extern __shared__ char sm[];
    u32 sb = smem_u32(sm);
    int tid = threadIdx.x;
    int wid = tid >> 5, lane = tid & 31;
    int b  = blockIdx.y;
    int s0 = blockIdx.x * 128;
    size_t tb = ((size_t)(b * gridDim.x + blockIdx.x)) * 32768;
    const float* Xb = X + (size_t)b * CC * S;

    stage_tile(sb + P0, wsc, tid);            // Ahi
    CP_COMMIT();
    {
        float rv[4];
        #pragma unroll
        for (int j = 0; j < 4; j++)
            rv[j] = NORM ? rms[(size_t)b * S + s0 + lane + j * 32] : 1.0f;
        #pragma unroll
        for (int i = 0; i < 16; i++) {
            int s = lane + (i & 3) * 32;
            int c0 = ((wid << 2) + (i >> 2)) * 4;
            float4 x4;
            x4.x = Xb[(size_t)(c0 + 0) * S + s0 + s];
            x4.y = Xb[(size_t)(c0 + 1) * S + s0 + s];
            x4.z = Xb[(size_t)(c0 + 2) * S + s0 + s];
            x4.w = Xb[(size_t)(c0 + 3) * S + s0 + s];
            if (NORM) {
                float r = rv[i & 3];
                x4.x *= r; x4.y *= r; x4.z *= r; x4.w *= r;
            }
            cvt_store4(sm, P1, P2, s, c0, x4);   // Bhi -> P1, Blo -> P2
        }
    }

    int m_blk = (wid & 3) * 32;
    int n_blk = (wid >> 2) * 64;
    float acc[2][8][4];
    #pragma unroll
    for (int i = 0; i < 2; i++)
        #pragma unroll
        for (int j = 0; j < 8; j++)
            #pragma unroll
            for (int q = 0; q < 4; q++) acc[i][j][q] = 0.f;

    u32 a_row = (u32)(m_blk + (lane & 15));
    u32 a_koff = (u32)((lane >> 4) << 3);
    u32 b_row = (u32)((lane & 7) + ((lane >> 4) << 3));
    u32 b_koff = (u32)(((lane >> 3) & 1) << 3);

    CP_WAIT0(); __syncthreads();
    mm_pass(sb + P0, sb + P1, acc, a_row, a_koff, b_row, b_koff, n_blk);   // Ahi*Bhi
    mm_pass(sb + P0, sb + P2, acc, a_row, a_koff, b_row, b_koff, n_blk);   // Ahi*Blo
    __syncthreads();
    stage_tile(sb + P2, wsc + 16384, tid);    // Alo
    CP_COMMIT(); CP_WAIT0(); __syncthreads();
    mm_pass(sb + P2, sb + P1, acc, a_row, a_koff, b_row, b_koff, n_blk);   // Alo*Bhi

    float scl = (EPI == 1) ? *sc_p : 0.f;
    u32* trans = (u32*)sm;
    if (OUTFMT >= 1) __syncthreads();
    #pragma unroll
    for (int i = 0; i < 2; i++) {
        #pragma unroll
        for (int j = 0; j < 8; j++) {
            int c = n_blk + j * 8 + (lane & 3) * 2;
            #pragma unroll
            for (int h = 0; h < 2; h++) {
                int o = m_blk + i * 16 + (lane >> 2) + h * 8;
                float bv = bias[o];
                float v0 = acc[i][j][h * 2 + 0] + bv;
                float v1 = acc[i][j][h * 2 + 1] + bv;
                if (ACT == 1) { v0 = silu_f(v0); v1 = silu_f(v1); }
                if (OUTFMT != 1) {
                    float* yp = Y + ((size_t)b * CC + o) * S + s0 + c;
                    float w0 = v0, w1 = v1;
                    if (EPI == 1) {
                        const float* ep = extra + ((size_t)b * CC + o) * S + s0 + c;
                        w0 += scl * ep[0]; w1 += scl * ep[1];
                    }
                    if (EPI == 2) { w0 += yp[0]; w1 += yp[1]; }
                    float2 ov; ov.x = w0; ov.y = w1;
                    *(float2*)yp = ov;
                }
                if (OUTFMT >= 1) {
                    trans[c * TP + o] = pack_hl(v0);
                    trans[(c + 1) * TP + o] = pack_hl(v1);
                }
            }
        }
    }
    if (OUTFMT >= 1) {
        __syncthreads();
        u16* thi = tout + tb;
        u16* tlo = thi + 16384;
        #pragma unroll
        for (int it = 0; it < 16; it++) {
            int idx = tid + it * 256;
            int s = idx >> 5, c0 = (idx & 31) * 4;
            uint4 w = *(const uint4*)(trans + s * TP + c0);
            u64 hv = (u64)(w.x & 0xffff) | ((u64)(w.y & 0xffff) << 16)
                   | ((u64)(w.z & 0xffff) << 32) | ((u64)(w.w & 0xffff) << 48);
            u64 lv = (u64)(w.x >> 16) | ((u64)(w.y >> 16) << 16)
                   | ((u64)(w.z >> 16) << 32) | ((u64)(w.w >> 16) << 48);
            *(u64*)(thi + s * 128 + c0) = hv;
            *(u64*)(tlo + s * 128 + c0) = lv;
        }
    }
}

// ================= GLU (fp32 input w/ rms, bf16 tile output) =================
#define GL_AAHI 0
#define GL_AALO (GL_AAHI + TILE_B)
#define GL_AGHI (GL_AALO + TILE_B)
#define GL_AGLO (GL_AGHI + TILE_B)
#define GL_BHI  (GL_AGLO + TILE_B)
#define GL_BLO  (GL_BHI  + TILE_B)
#define GL_SMEM (GL_BLO  + TILE_B)

__global__ __launch_bounds__(256)
void glu_mm(const float* __restrict__ X, const u16* __restrict__ wsc,
            const float* __restrict__ bias, u16* __restrict__ tout,
            const float* __restrict__ rms, int S)
{
    extern __shared__ char sm[];
    u32 sb = smem_u32(sm);
    int tid = threadIdx.x;
    int wid = tid >> 5, lane = tid & 31;
    int b  = blockIdx.y;
    int s0 = blockIdx.x * 128;
    size_t tb = ((size_t)(b * gridDim.x + blockIdx.x)) * 32768;
    const float* Xb = X + (size_t)b * CC * S;

    stage_tile(sb + GL_AAHI, wsc, tid);
    stage_tile(sb + GL_AGHI, wsc + 16384, tid);
    stage_tile(sb + GL_AALO, wsc + 32768, tid);
    stage_tile(sb + GL_AGLO, wsc + 49152, tid);
    CP_COMMIT();
    {
        float rv[4];
        #pragma unroll
        for (int j = 0; j < 4; j++)
            rv[j] = rms[(size_t)b * S + s0 + lane + j * 32];
        #pragma unroll
        for (int i = 0; i < 16; i++) {
            int s = lane + (i & 3) * 32;
            int c0 = ((wid << 2) + (i >> 2)) * 4;
            float4 x4;
            x4.x = Xb[(size_t)(c0 + 0) * S + s0 + s];
            x4.y = Xb[(size_t)(c0 + 1) * S + s0 + s];
            x4.z = Xb[(size_t)(c0 + 2) * S + s0 + s];
            x4.w = Xb[(size_t)(c0 + 3) * S + s0 + s];
            float r = rv[i & 3];
            x4.x *= r; x4.y *= r; x4.z *= r; x4.w *= r;
            cvt_store4(sm, GL_BHI, GL_BLO, s, c0, x4);
        }
    }
    CP_WAIT0();
    __syncthreads();

    int m_blk = (wid & 3) * 32;
    int n_blk = (wid >> 2) * 64;
    float acca[2][8][4], accg[2][8][4];
    #pragma unroll
    for (int i = 0; i < 2; i++)
        #pragma unroll
        for (int j = 0; j < 8; j++)
            #pragma unroll
            for (int q = 0; q < 4; q++) { acca[i][j][q] = 0.f; accg[i][j][q] = 0.f; }

    u32 a_row = (u32)(m_blk + (lane & 15));
    u32 a_koff = (u32)((lane >> 4) << 3);
    u32 b_row = (u32)((lane & 7) + ((lane >> 4) << 3));
    u32 b_koff = (u32)(((lane >> 3) & 1) << 3);

    const u32 aab[3] = {sb + GL_AAHI, sb + GL_AAHI, sb + GL_AALO};
    const u32 agb[3] = {sb + GL_AGHI, sb + GL_AGHI, sb + GL_AGLO};
    const u32 bbb[3] = {sb + GL_BHI,  sb + GL_BLO,  sb + GL_BHI };

    #pragma unroll
    for (int p = 0; p < 3; p++) {
        mm_pass(aab[p], bbb[p], acca, a_row, a_koff, b_row, b_koff, n_blk);
        mm_pass(agb[p], bbb[p], accg, a_row, a_koff, b_row, b_koff, n_blk);
    }

    u32* trans = (u32*)sm;
    __syncthreads();
    #pragma unroll
    for (int i = 0; i < 2; i++) {
        #pragma unroll
        for (int j = 0; j < 8; j++) {
            int c = n_blk + j * 8 + (lane & 3) * 2;
            #pragma unroll
            for (int h = 0; h < 2; h++) {
                int o = m_blk + i * 16 + (lane >> 2) + h * 8;
                float ba = bias[o], bg = bias[CC + o];
                float v0 = (acca[i][j][h * 2 + 0] + ba) * silu_f(accg[i][j][h * 2 + 0] + bg);
                float v1 = (acca[i][j][h * 2 + 1] + ba) * silu_f(accg[i][j][h * 2 + 1] + bg);
                trans[c * TP + o] = pack_hl(v0);
                trans[(c + 1) * TP + o] = pack_hl(v1);
            }
        }
    }
    __syncthreads();
    {
        u16* thi = tout + tb;
        u16* tlo = thi + 16384;
        #pragma unroll
        for (int it = 0; it < 16; it++) {
            int idx = tid + it * 256;
            int s = idx >> 5, c0 = (idx & 31) * 4;
            uint4 w = *(const uint4*)(trans + s * TP + c0);
            u64 hv = (u64)(w.x & 0xffff) | ((u64)(w.y & 0xffff) << 16)
                   | ((u64)(w.z & 0xffff) << 32) | ((u64)(w.w & 0xffff) << 48);
            u64 lv = (u64)(w.x >> 16) | ((u64)(w.y >> 16) << 16)
                   | ((u64)(w.z >> 16) << 32) | ((u64)(w.w >> 16) << 48);
            *(u64*)(thi + s * 128 + c0) = hv;
            *(u64*)(tlo + s * 128 + c0) = lv;
        }
    }
}

// ---------------- Attention (SIMT) ----------------
#define ATT_SMEM_FLOATS (128*72 + 2*64*136)
#define ATT_SMEM_BYTES  (ATT_SMEM_FLOATS * 4)

__global__ __launch_bounds__(256)
void attn_kernel(const float* __restrict__ q, const float* __restrict__ kmat,
                 const float* __restrict__ vmat, const float* __restrict__ basis,
                 const float* __restrict__ ss_p, const float* __restrict__ ps_p,
                 float* __restrict__ att)
{
    extern __shared__ float smf[];
    float* Ks  = smf;
    float* Qs  = smf + 128 * 72;
    float* Vt  = Qs;
    float* Wsm = Qs + 64 * 136;

    int fb = blockIdx.x * 128;
    int t  = blockIdx.y;
    int b  = blockIdx.z;
    int tid = threadIdx.x;
    int tx = tid & 15, ty = tid >> 4;

    const float* kb = kmat + (size_t)b * CC * S_LAT + t * KK;
    #pragma unroll
    for (int it = 0; it < 8; it++) {
        int idx = tid + it * 256;
        int c = idx >> 4, kq = idx & 15;
        float4 v = *(const float4*)(kb + (size_t)c * S_LAT + kq * 4);
        *(float4*)&Ks[c * 72 + kq * 4] = v;
    }
    const float* qb = q + (size_t)b * CC * S_SIDE + t * FF + fb;
    #pragma unroll
    for (int it = 0; it < 16; it++) {
        int idx = tid + it * 256;
        int c = idx >> 5, fq = idx & 31;
        float4 v = *(const float4*)(qb + (size_t)c * S_SIDE + fq * 4);
        *(float4*)&Qs[c * 128 + fq * 4] = v;
    }
    __syncthreads();

    u64 sc2[8][2];
    #pragma unroll
    for (int i = 0; i < 8; i++) { sc2[i][0] = 0ull; sc2[i][1] = 0ull; }

    #pragma unroll 4
    for (int c = 0; c < CC; c++) {
        u64 kp0 = *(const u64*)&Ks[c * 72 + tx * 4];
        u64 kp1 = *(const u64*)&Ks[c * 72 + tx * 4 + 2];
        float4 q0 = *(const float4*)&Qs[c * 128 + ty * 8];
        float4 q1 = *(const float4*)&Qs[c * 128 + ty * 8 + 4];
        u64 qd[8] = {dup2(q0.x),dup2(q0.y),dup2(q0.z),dup2(q0.w),
                     dup2(q1.x),dup2(q1.y),dup2(q1.z),dup2(q1.w)};
        #pragma unroll
        for (int i = 0; i < 8; i++) {
            fma2(sc2[i][0], qd[i], kp0);
            fma2(sc2[i][1], qd[i], kp1);
        }
    }
    float sc[8][4];
    #pragma unroll
    for (int i = 0; i < 8; i++) {
        float2 p0 = unpack2(sc2[i][0]);
        float2 p1 = unpack2(sc2[i][1]);
        sc[i][0] = p0.x; sc[i][1] = p0.y; sc[i][2] = p1.x; sc[i][3] = p1.y;
    }
    float ssv = *ss_p, psv = *ps_p;
    #pragma unroll
    for (int i = 0; i < 8; i++)
        #pragma unroll
        for (int j = 0; j < 4; j++)
            sc[i][j] = sc[i][j] * ssv
                     + basis[(tx * 4 + j) * FF + fb + ty * 8 + i] * psv;
    __syncthreads();

    float w[8][4];
    #pragma unroll
    for (int i = 0; i < 8; i++) {
        float m = fmaxf(fmaxf(sc[i][0], sc[i][1]), fmaxf(sc[i][2], sc[i][3]));
        #pragma unroll
        for (int off = 8; off >= 1; off >>= 1)
            m = fmaxf(m, __shfl_xor_sync(0xffffffffu, m, off));
        float e0 = __expf(sc[i][0] - m);
        float e1 = __expf(sc[i][1] - m);
        float e2 = __expf(sc[i][2] - m);
        float e3 = __expf(sc[i][3] - m);
        float s = e0 + e1 + e2 + e3;
        #pragma unroll
        for (int off = 8; off >= 1; off >>= 1)
            s += __shfl_xor_sync(0xffffffffu, s, off);
        float inv = 1.0f / s;
        w[i][0] = e0 * inv; w[i][1] = e1 * inv;
        w[i][2] = e2 * inv; w[i][3] = e3 * inv;
    }
    #pragma unroll
    for (int i = 0; i < 8; i++)
        #pragma unroll
        for (int j = 0; j < 4; j++)
            Wsm[(tx * 4 + j) * 136 + ty * 8 + i] = w[i][j];

    const float* vb = vmat + (size_t)b * CC * S_LAT + t * KK;
    #pragma unroll
    for (int it = 0; it < 8; it++) {
        int idx = tid + it * 256;
        int c = idx >> 4, kq = idx & 15;
        float4 v = *(const float4*)(vb + (size_t)c * S_LAT + kq * 4);
        Vt[(kq * 4 + 0) * 136 + c] = v.x;
        Vt[(kq * 4 + 1) * 136 + c] = v.y;
        Vt[(kq * 4 + 2) * 136 + c] = v.z;
        Vt[(kq * 4 + 3) * 136 + c] = v.w;
    }
    __syncthreads();

    u64 ac2[4][8];
    #pragma unroll
    for (int i = 0; i < 4; i++)
        #pragma unroll
        for (int j = 0; j < 8; j++) ac2[i][j] = 0ull;

    #pragma unroll 4
    for (int k = 0; k < KK; k++) {
        u64 vp[4];
        #pragma unroll
        for (int i = 0; i < 4; i++)
            vp[i] = *(const u64*)&Vt[k * 136 + ty * 8 + 2 * i];
        float4 w0 = *(const float4*)&Wsm[k * 136 + tx * 8];
        float4 w1 = *(const float4*)&Wsm[k * 136 + tx * 8 + 4];
        u64 wd[8] = {dup2(w0.x),dup2(w0.y),dup2(w0.z),dup2(w0.w),
                     dup2(w1.x),dup2(w1.y),dup2(w1.z),dup2(w1.w)};
        #pragma unroll
        for (int i = 0; i < 4; i++)
            #pragma unroll
            for (int j = 0; j < 8; j++)
                fma2(ac2[i][j], vp[i], wd[j]);
    }
    #pragma unroll
    for (int i = 0; i < 4; i++) {
        float r0[8], r1[8];
        #pragma unroll
        for (int j = 0; j < 8; j++) {
            float2 p = unpack2(ac2[i][j]);
            r0[j] = p.x; r1[j] = p.y;
        }
        #pragma unroll
        for (int half = 0; half < 2; half++) {
            int c = ty * 8 + 2 * i + half;
            float* rr = half ? r1 : r0;
            float* orow = att + (((size_t)b * CC + c) * TT + t) * FF + fb + tx * 8;
            *(float4*)(orow + 0) = make_float4(rr[0], rr[1], rr[2], rr[3]);
            *(float4*)(orow + 4) = make_float4(rr[4], rr[5], rr[6], rr[7]);
        }
    }
}

// ---------------- host ----------------
extern "C" void kernel_launch(void* const* d_in, const int* in_sizes, int n_in,
                              void* d_out, int out_size)
{
    const float* latent     = (const float*)d_in[0];
    const float* side       = (const float*)d_in[1];
    const float* basis      = (const float*)d_in[2];
    const float* lp_gamma   = (const float*)d_in[3];
    const float* lp_w       = (const float*)d_in[4];
    const float* lp_b       = (const float*)d_in[5];
    const float* qn_gamma   = (const float*)d_in[6];
    const float* qmlp_in_w  = (const float*)d_in[7];
    const float* qmlp_in_b  = (const float*)d_in[8];
    const float* qmlp_out_w = (const float*)d_in[9];
    const float* qmlp_out_b = (const float*)d_in[10];
    const float* q_w        = (const float*)d_in[11];
    const float* q_b        = (const float*)d_in[12];
    const float* k_w        = (const float*)d_in[13];
    const float* k_b        = (const float*)d_in[14];
    const float* v_w        = (const float*)d_in[15];
    const float* v_b        = (const float*)d_in[16];
    const float* o_w        = (const float*)d_in[17];
    const float* o_b        = (const float*)d_in[18];
    const float* ffn_gamma  = (const float*)d_in[19];
    const float* ffn_in_w   = (const float*)d_in[20];
    const float* ffn_in_b   = (const float*)d_in[21];
    const float* ffn_out_w  = (const float*)d_in[22];
    const float* ffn_out_b  = (const float*)d_in[23];
    const float* score_sc   = (const float*)d_in[24];
    const float* prior_sc   = (const float*)d_in[25];
    const float* qskip_sc   = (const float*)d_in[26];
    float* out = (float*)d_out;

    float *buf1, *buf2, *buf3, *rmsb, *rmsL, *kmat, *vmat;
    u16 *tA, *tB, *tL, *wbf;
    cudaGetSymbolAddress((void**)&buf1, g_buf1);
    cudaGetSymbolAddress((void**)&buf2, g_buf2);
    cudaGetSymbolAddress((void**)&buf3, g_buf3);
    cudaGetSymbolAddress((void**)&rmsb, g_rms);
    cudaGetSymbolAddress((void**)&rmsL, g_rmsL);
    cudaGetSymbolAddress((void**)&kmat, g_k);
    cudaGetSymbolAddress((void**)&vmat, g_v);
    cudaGetSymbolAddress((void**)&tA,   g_tA);
    cudaGetSymbolAddress((void**)&tB,   g_tB);
    cudaGetSymbolAddress((void**)&tL,   g_tL);
    cudaGetSymbolAddress((void**)&wbf,  g_wbf);

    cudaFuncSetAttribute(attn_kernel, cudaFuncAttributeMaxDynamicSharedMemorySize, ATT_SMEM_BYTES);
    cudaFuncSetAttribute(gemm_f32in<1,1,0,1>, cudaFuncAttributeMaxDynamicSharedMemorySize, GT_SMEM);
    cudaFuncSetAttribute(gemm_f32in<0,0,1,0>, cudaFuncAttributeMaxDynamicSharedMemorySize, GT_SMEM);
    cudaFuncSetAttribute(gemm_bfin<0,0>, cudaFuncAttributeMaxDynamicSharedMemorySize, GT_SMEM);
    cudaFuncSetAttribute(gemm_bfin<0,2>, cudaFuncAttributeMaxDynamicSharedMemorySize, GT_SMEM);
    cudaFuncSetAttribute(gemm_bfin<2,0>, cudaFuncAttributeMaxDynamicSharedMemorySize, GT_SMEM);
    cudaFuncSetAttribute(glu_mm, cudaFuncAttributeMaxDynamicSharedMemorySize, GL_SMEM);

    dim3 blk(256);

    // 0: fused weight pre-convert
    convert_all<<<704, blk>>>(lp_w, k_w, v_w, qmlp_out_w, q_w, o_w, ffn_out_w,
                              qmlp_in_w, ffn_in_w, lp_gamma, qn_gamma, ffn_gamma, wbf);

    // 1,2: inv-rms for latent (separate buffer!) and side
    rms_scale_kernel<<<dim3(S_LAT/1024, BB), blk>>>(latent, rmsL, S_LAT);
    rms_scale_kernel<<<dim3(S_SIDE/1024, BB), blk>>>(side, rmsb, S_SIDE);

    // 3: latent_pre
    gemm_f32in<1,1,0,1><<<dim3(S_LAT/128, BB), blk, GT_SMEM>>>(
        latent, wbf + WLP, lp_b, nullptr, nullptr, nullptr, rmsL, tL, S_LAT);

    // 4: glu1 (side rms)
    glu_mm<<<dim3(S_SIDE/128, BB), blk, GL_SMEM>>>(side, wbf + WQI, qmlp_in_b, tA, rmsb, S_SIDE);

    // 5: qmlp_out (profiled slot)
    gemm_bfin<0,2><<<dim3(S_SIDE/128, BB), blk, GT_SMEM>>>(
        wbf + WQO, qmlp_out_b, tA, tB, buf3, nullptr, nullptr, S_SIDE);

    // 6,7: k, v
    gemm_bfin<0,0><<<dim3(S_LAT/128, BB), blk, GT_SMEM>>>(
        wbf + WK, k_b, tL, nullptr, kmat, nullptr, nullptr, S_LAT);
    gemm_bfin<0,0><<<dim3(S_LAT/128, BB), blk, GT_SMEM>>>(
        wbf + WV, v_b, tL, nullptr, vmat, nullptr, nullptr, S_LAT);

    // 8: q
    gemm_bfin<0,0><<<dim3(S_SIDE/128, BB), blk, GT_SMEM>>>(
        wbf + WQ, q_b, tB, nullptr, buf2, nullptr, nullptr, S_SIDE);

    // 9: attention
    attn_kernel<<<dim3(FF/128, TT, BB), blk, ATT_SMEM_BYTES>>>(
        buf2, kmat, vmat, basis, score_sc, prior_sc, buf1);

    // 10: o-proj + query skip
    gemm_f32in<0,0,1,0><<<dim3(S_SIDE/128, BB), blk, GT_SMEM>>>(
        buf1, wbf + WO, o_b, out, buf3, qskip_sc, nullptr, nullptr, S_SIDE);

    // 11,12,13: FFN
    rms_scale_kernel<<<dim3(S_SIDE/1024, BB), blk>>>(out, rmsb, S_SIDE);
    glu_mm<<<dim3(S_SIDE/128, BB), blk, GL_SMEM>>>(out, wbf + WFI, ffn_in_b, tA, rmsb, S_SIDE);
    gemm_bfin<2,0><<<dim3(S_SIDE/128, BB), blk, GT_SMEM>>>(
        wbf + WFO, ffn_out_b, tA, nullptr, out, nullptr, nullptr, S_SIDE);
}

// round 11
// speedup vs baseline: 1.3398x; 1.3398x over previous
#include <cuda_runtime.h>
#include <cuda_bf16.h>
#include <cstdint>

#define BB 8
#define CC 128
#define TT 128
#define FF 512
#define KK 64
#define S_SIDE (TT*FF)
#define S_LAT  (TT*KK)

typedef unsigned long long u64;
typedef unsigned int u32;
typedef unsigned short u16;

// ---------------- scratch ----------------
__device__ float g_buf1[BB*CC*S_SIDE];            // attention out
__device__ float g_buf2[BB*CC*S_SIDE];            // q (fp32)
__device__ float g_buf3[BB*CC*S_SIDE];            // query_h (fp32, for skip)
__device__ float g_rms [BB*S_SIDE];               // side/ffn inv-rms
__device__ float g_rmsL[BB*S_LAT];                // latent inv-rms
__device__ float g_k  [BB*CC*S_LAT];
__device__ float g_v  [BB*CC*S_LAT];
__device__ float g_qbias[CC];                     // folded q bias

// bf16 hi/lo tile buffers: per (b,tile128): 16384 hi + 16384 lo u16
__device__ u16 g_tA[8*512*32768];                 // glu1 out / glu2 out
__device__ u16 g_tL[8*64*32768];                  // latent_h

// pre-converted weights (hi block then lo block per matrix)
#define WLP 0
#define WK  32768
#define WV  65536
#define WQO 98304
#define WQ  131072
#define WO  163840
#define WFO 196608
#define WQI 229376
#define WFI 294912
__device__ u16 g_wbf[360448];

__device__ __forceinline__ float silu_f(float x) { return x / (1.0f + __expf(-x)); }
__device__ __forceinline__ u64 dup2(float v) {
    u64 r; asm("mov.b64 %0, {%1, %2};" : "=l"(r) : "f"(v), "f"(v)); return r;
}
__device__ __forceinline__ void fma2(u64& d, u64 a, u64 b) {
    asm("fma.rn.f32x2 %0, %1, %2, %0;" : "+l"(d) : "l"(a), "l"(b));
}
__device__ __forceinline__ float2 unpack2(u64 v) {
    float2 r; asm("mov.b64 {%0, %1}, %2;" : "=f"(r.x), "=f"(r.y) : "l"(v)); return r;
}
__device__ __forceinline__ u32 smem_u32(const void* p) {
    u32 a;
    asm("{ .reg .u64 t; cvta.to.shared.u64 t, %1; cvt.u32.u64 %0, t; }" : "=r"(a) : "l"(p));
    return a;
}

// ---------------- mma.sync helpers ----------------
__device__ __forceinline__ void ldsm4(u32* r, u32 addr) {
    asm volatile("ldmatrix.sync.aligned.m8n8.x4.shared.b16 {%0,%1,%2,%3}, [%4];"
                 : "=r"(r[0]), "=r"(r[1]), "=r"(r[2]), "=r"(r[3]) : "r"(addr));
}
__device__ __forceinline__ void mma16816(float* d, const u32* a, const u32* b) {
    asm volatile("mma.sync.aligned.m16n8k16.row.col.f32.bf16.bf16.f32 "
                 "{%0,%1,%2,%3}, {%4,%5,%6,%7}, {%8,%9}, {%0,%1,%2,%3};"
                 : "+f"(d[0]), "+f"(d[1]), "+f"(d[2]), "+f"(d[3])
                 : "r"(a[0]), "r"(a[1]), "r"(a[2]), "r"(a[3]), "r"(b[0]), "r"(b[1]));
}
__device__ __forceinline__ void cpa16(u32 saddr, const void* g) {
    asm volatile("cp.async.cg.shared.global [%0], [%1], 16;" :: "r"(saddr), "l"(g));
}
#define CP_COMMIT() asm volatile("cp.async.commit_group;" ::: "memory")
#define CP_WAIT0()  asm volatile("cp.async.wait_group 0;" ::: "memory")

#define TSTR  272
#define TILE_B (128*TSTR)
#define TP 132

// fp32 -> bf16 hi/lo split, store 4 cols to padded smem tiles
__device__ __forceinline__ void cvt_store4(char* smem, u32 hi_base, u32 lo_base,
                                           int row, int col, float4 x) {
    __nv_bfloat16 h0 = __float2bfloat16_rn(x.x); float r0 = x.x - __bfloat162float(h0);
    __nv_bfloat16 h1 = __float2bfloat16_rn(x.y); float r1 = x.y - __bfloat162float(h1);
    __nv_bfloat16 h2 = __float2bfloat16_rn(x.z); float r2 = x.z - __bfloat162float(h2);
    __nv_bfloat16 h3 = __float2bfloat16_rn(x.w); float r3 = x.w - __bfloat162float(h3);
    __nv_bfloat16 l0 = __float2bfloat16_rn(r0);
    __nv_bfloat16 l1 = __float2bfloat16_rn(r1);
    __nv_bfloat16 l2 = __float2bfloat16_rn(r2);
    __nv_bfloat16 l3 = __float2bfloat16_rn(r3);
    u64 hv = (u64)*(u16*)&h0 | ((u64)*(u16*)&h1 << 16) | ((u64)*(u16*)&h2 << 32) | ((u64)*(u16*)&h3 << 48);
    u64 lv = (u64)*(u16*)&l0 | ((u64)*(u16*)&l1 << 16) | ((u64)*(u16*)&l2 << 32) | ((u64)*(u16*)&l3 << 48);
    u32 o = (u32)(row * TSTR + col * 2);
    *(u64*)(smem + hi_base + o) = hv;
    *(u64*)(smem + lo_base + o) = lv;
}

__device__ __forceinline__ u32 pack_hl(float v) {
    __nv_bfloat16 h = __float2bfloat16_rn(v);
    float l = v - __bfloat162float(h);
    __nv_bfloat16 lo = __float2bfloat16_rn(l);
    return (u32)*(u16*)&h | ((u32)*(u16*)&lo << 16);
}

// stage one contiguous 128x128 u16 tile into TSTR-padded smem via cp.async
__device__ __forceinline__ void stage_tile(u32 sbase, const u16* g, int tid) {
    #pragma unroll
    for (int it = 0; it < 8; it++) {
        int idx = tid + it * 256;
        int r = idx >> 4, ch = idx & 15;
        cpa16(sbase + r * TSTR + ch * 16, g + r * 128 + ch * 8);
    }
}
// stage a 64-row x 128-col u16 tile
__device__ __forceinline__ void stage_tile64(u32 sbase, const u16* g, int tid) {
    #pragma unroll
    for (int it = 0; it < 4; it++) {
        int idx = tid + it * 256;
        int r = idx >> 4, ch = idx & 15;
        cpa16(sbase + r * TSTR + ch * 16, g + r * 128 + ch * 8);
    }
}

// one k=128 HMMA pass; warp covers 32m x 64n
__device__ __forceinline__ void mm_pass(u32 ab, u32 bb, float (*acc)[8][4],
                                        u32 a_row, u32 a_koff, u32 b_row, u32 b_koff,
                                        int n_blk)
{
    #pragma unroll
    for (int ks = 0; ks < 8; ks++) {
        int k0 = ks * 16;
        u32 af[2][4], bf[4][4];
        #pragma unroll
        for (int i = 0; i < 2; i++)
            ldsm4(af[i], ab + (a_row + i * 16) * TSTR + (k0 + a_koff) * 2);
        #pragma unroll
        for (int j = 0; j < 4; j++)
            ldsm4(bf[j], bb + (n_blk + j * 16 + b_row) * TSTR + (k0 + b_koff) * 2);
        #pragma unroll
        for (int i = 0; i < 2; i++)
            #pragma unroll
            for (int j = 0; j < 8; j++)
                mma16816(acc[i][j], af[i], &bf[j >> 1][(j & 1) * 2]);
    }
}

// one k=128 HMMA pass; warp covers 32m x 32n (for 64-col B tiles)
__device__ __forceinline__ void mm_pass64(u32 ab, u32 bb, float (*acc)[4][4],
                                          u32 a_row, u32 a_koff, u32 b_row, u32 b_koff,
                                          int n_blk)
{
    #pragma unroll
    for (int ks = 0; ks < 8; ks++) {
        int k0 = ks * 16;
        u32 af[2][4], bf[2][4];
        #pragma unroll
        for (int i = 0; i < 2; i++)
            ldsm4(af[i], ab + (a_row + i * 16) * TSTR + (k0 + a_koff) * 2);
        #pragma unroll
        for (int j = 0; j < 2; j++)
            ldsm4(bf[j], bb + (n_blk + j * 16 + b_row) * TSTR + (k0 + b_koff) * 2);
        #pragma unroll
        for (int i = 0; i < 2; i++)
            #pragma unroll
            for (int j = 0; j < 4; j++)
                mma16816(acc[i][j], af[i], &bf[j >> 1][(j & 1) * 2]);
    }
}

// ---------------- fused weight pre-convert (gamma folded) ----------------
__global__ __launch_bounds__(256)
void convert_all(const float* __restrict__ lp_w, const float* __restrict__ k_w,
                 const float* __restrict__ v_w,  const float* __restrict__ qo_w,
                 const float* __restrict__ o_w,  const float* __restrict__ fo_w,
                 const float* __restrict__ qi_w, const float* __restrict__ fi_w,
                 const float* __restrict__ lp_g, const float* __restrict__ qn_g,
                 const float* __restrict__ ffn_g, u16* __restrict__ dst)
{
    int bid = blockIdx.x;
    const float* src; const float* gamma = nullptr; int off, n, lb;
    if (bid < 384) {
        int seg = bid >> 6; lb = bid & 63; n = 16384;
        switch (seg) {
            case 0: src = lp_w; gamma = lp_g; off = WLP; break;
            case 1: src = k_w;  off = WK;  break;
            case 2: src = v_w;  off = WV;  break;
            case 3: src = qo_w; off = WQO; break;
            case 4: src = o_w;  off = WO;  break;
            default: src = fo_w; off = WFO; break;
        }
    } else if (bid < 512) {
        lb = bid - 384; src = qi_w; gamma = qn_g; off = WQI; n = 32768;
    } else {
        lb = bid - 512; src = fi_w; gamma = ffn_g; off = WFI; n = 32768;
    }
    int idx = lb * 256 + threadIdx.x;
    if (idx >= n) return;
    float v = src[idx];
    if (gamma) v *= gamma[idx & 127];
    __nv_bfloat16 h = __float2bfloat16_rn(v);
    float l = v - __bfloat162float(h);
    __nv_bfloat16 lo = __float2bfloat16_rn(l);
    dst[off + idx] = *(u16*)&h;
    dst[off + n + idx] = *(u16*)&lo;
}

// ---------------- fold q through qmlp_out: Wq' = q_w @ qo_w, b' = q_w@qo_b + q_b ----------------
__global__ __launch_bounds__(256)
void qfold_prep(const float* __restrict__ qw, const float* __restrict__ qow,
                const float* __restrict__ qob, const float* __restrict__ qb,
                u16* __restrict__ dst, float* __restrict__ qbias)
{
    int idx = blockIdx.x * 256 + threadIdx.x;   // 0..16383
    int o = idx >> 7, c = idx & 127;
    float s = 0.f;
    #pragma unroll 4
    for (int m = 0; m < 128; m++)
        s += qw[o * 128 + m] * qow[m * 128 + c];
    __nv_bfloat16 h = __float2bfloat16_rn(s);
    float l = s - __bfloat162float(h);
    __nv_bfloat16 lo = __float2bfloat16_rn(l);
    dst[idx] = *(u16*)&h;
    dst[16384 + idx] = *(u16*)&lo;
    if (c == 0) {
        float t = qb[o];
        #pragma unroll 4
        for (int m = 0; m < 128; m++)
            t += qw[o * 128 + m] * qob[m];
        qbias[o] = t;
    }
}

// ---------------- inv-RMS ----------------
__global__ __launch_bounds__(256)
void rms_scale_kernel(const float* __restrict__ X, float* __restrict__ R, int S)
{
    int b = blockIdx.y;
    int s = blockIdx.x * 1024 + threadIdx.x * 4;
    const float* xb = X + (size_t)b * CC * S + s;
    float4 acc = make_float4(0.f, 0.f, 0.f, 0.f);
    #pragma unroll 4
    for (int c = 0; c < CC; c++) {
        float4 v = *(const float4*)(xb + (size_t)c * S);
        acc.x += v.x * v.x; acc.y += v.y * v.y;
        acc.z += v.z * v.z; acc.w += v.w * v.w;
    }
    const float inv = 1.0f / CC;
    float4 r;
    r.x = rsqrtf(acc.x * inv + 1e-6f);
    r.y = rsqrtf(acc.y * inv + 1e-6f);
    r.z = rsqrtf(acc.z * inv + 1e-6f);
    r.w = rsqrtf(acc.w * inv + 1e-6f);
    *(float4*)(R + (size_t)b * S + s) = r;
}

// ================= 64-col bf-tile GEMM: 2 CTAs/SM, 4 independent buffers =================
#define B64_AHI 0
#define B64_ALO (128*TSTR)
#define B64_BHI (2*128*TSTR)
#define B64_BLO (2*128*TSTR + 64*TSTR)
#define B64_SMEM (2*128*TSTR + 2*64*TSTR)

// EPI: 0 none, 2 += Y
template<int EPI>
__global__ __launch_bounds__(256, 2)
void gemm_bf64(const u16* __restrict__ wsc, const float* __restrict__ bias,
               const u16* __restrict__ tin, float* __restrict__ Y, int S)
{
    extern __shared__ char sm[];
    u32 sb = smem_u32(sm);
    int tid = threadIdx.x;
    int wid = tid >> 5, lane = tid & 31;
    int b   = blockIdx.y;
    int blk = blockIdx.x;
    int s0  = blk * 64;
    int nt128 = gridDim.x >> 1;
    size_t tb = ((size_t)(b * nt128 + (blk >> 1))) * 32768 + (size_t)(blk & 1) * 8192;

    stage_tile  (sb + B64_AHI, wsc, tid);
    stage_tile  (sb + B64_ALO, wsc + 16384, tid);
    stage_tile64(sb + B64_BHI, tin + tb, tid);
    stage_tile64(sb + B64_BLO, tin + tb + 16384, tid);
    CP_COMMIT();

    int m_blk = (wid & 3) * 32;
    int n_blk = (wid >> 2) * 32;
    float acc[2][4][4];
    #pragma unroll
    for (int i = 0; i < 2; i++)
        #pragma unroll
        for (int j = 0; j < 4; j++)
            #pragma unroll
            for (int q = 0; q < 4; q++) acc[i][j][q] = 0.f;

    u32 a_row = (u32)(m_blk + (lane & 15));
    u32 a_koff = (u32)((lane >> 4) << 3);
    u32 b_row = (u32)((lane & 7) + ((lane >> 4) << 3));
    u32 b_koff = (u32)(((lane >> 3) & 1) << 3);

    CP_WAIT0(); __syncthreads();
    mm_pass64(sb + B64_AHI, sb + B64_BHI, acc, a_row, a_koff, b_row, b_koff, n_blk);
    mm_pass64(sb + B64_AHI, sb + B64_BLO, acc, a_row, a_koff, b_row, b_koff, n_blk);
    mm_pass64(sb + B64_ALO, sb + B64_BHI, acc, a_row, a_koff, b_row, b_koff, n_blk);

    #pragma unroll
    for (int i = 0; i < 2; i++) {
        #pragma unroll
        for (int j = 0; j < 4; j++) {
            int c = n_blk + j * 8 + (lane & 3) * 2;
            #pragma unroll
            for (int h = 0; h < 2; h++) {
                int o = m_blk + i * 16 + (lane >> 2) + h * 8;
                float bv = bias[o];
                float v0 = acc[i][j][h * 2 + 0] + bv;
                float v1 = acc[i][j][h * 2 + 1] + bv;
                float* yp = Y + ((size_t)b * CC + o) * S + s0 + c;
                if (EPI == 2) { v0 += yp[0]; v1 += yp[1]; }
                float2 ov; ov.x = v0; ov.y = v1;
                *(float2*)yp = ov;
            }
        }
    }
}

// ================= GEMM, fp32 input (R7 4-buffer layout, 1 CTA) =================
#define GT_AHI 0
#define GT_ALO (GT_AHI + TILE_B)
#define GT_BHI (GT_ALO + TILE_B)
#define GT_BLO (GT_BHI + TILE_B)
#define GT_SMEM (GT_BLO + TILE_B)

template<int NORM, int ACT, int EPI, int OUTFMT>
__global__ __launch_bounds__(256)
void gemm_f32in(const float* __restrict__ X, const u16* __restrict__ wsc,
                const float* __restrict__ bias, float* __restrict__ Y,
                const float* __restrict__ extra, const float* __restrict__ sc_p,
                const float* __restrict__ rms, u16* __restrict__ tout, int S)
{
    extern __shared__ char sm[];
    u32 sb = smem_u32(sm);
    int tid = threadIdx.x;
    int wid = tid >> 5, lane = tid & 31;
    int b  = blockIdx.y;
    int s0 = blockIdx.x * 128;
    size_t tb = ((size_t)(b * gridDim.x + blockIdx.x)) * 32768;
    const float* Xb = X + (size_t)b * CC * S;

    stage_tile(sb + GT_AHI, wsc, tid);
    stage_tile(sb + GT_ALO, wsc + 16384, tid);
    CP_COMMIT();
    {
        float rv[4];
        #pragma unroll
        for (int j = 0; j < 4; j++)
            rv[j] = NORM ? rms[(size_t)b * S + s0 + lane + j * 32] : 1.0f;
        #pragma unroll
        for (int i = 0; i < 16; i++) {
            int s = lane + (i & 3) * 32;
            int c0 = ((wid << 2) + (i >> 2)) * 4;
            float4 x4;
            x4.x = Xb[(size_t)(c0 + 0) * S + s0 + s];
            x4.y = Xb[(size_t)(c0 + 1) * S + s0 + s];
            x4.z = Xb[(size_t)(c0 + 2) * S + s0 + s];
            x4.w = Xb[(size_t)(c0 + 3) * S + s0 + s];
            if (NORM) {
                float r = rv[i & 3];
                x4.x *= r; x4.y *= r; x4.z *= r; x4.w *= r;
            }
            cvt_store4(sm, GT_BHI, GT_BLO, s, c0, x4);
        }
    }
    CP_WAIT0();
    __syncthreads();

    int m_blk = (wid & 3) * 32;
    int n_blk = (wid >> 2) * 64;
    float acc[2][8][4];
    #pragma unroll
    for (int i = 0; i < 2; i++)
        #pragma unroll
        for (int j = 0; j < 8; j++)
            #pragma unroll
            for (int q = 0; q < 4; q++) acc[i][j][q] = 0.f;

    u32 a_row = (u32)(m_blk + (lane & 15));
    u32 a_koff = (u32)((lane >> 4) << 3);
    u32 b_row = (u32)((lane & 7) + ((lane >> 4) << 3));
    u32 b_koff = (u32)(((lane >> 3) & 1) << 3);

    mm_pass(sb + GT_AHI, sb + GT_BHI, acc, a_row, a_koff, b_row, b_koff, n_blk);
    mm_pass(sb + GT_AHI, sb + GT_BLO, acc, a_row, a_koff, b_row, b_koff, n_blk);
    mm_pass(sb + GT_ALO, sb + GT_BHI, acc, a_row, a_koff, b_row, b_koff, n_blk);

    float scl = (EPI == 1) ? *sc_p : 0.f;
    u32* trans = (u32*)sm;
    if (OUTFMT >= 1) __syncthreads();
    #pragma unroll
    for (int i = 0; i < 2; i++) {
        #pragma unroll
        for (int j = 0; j < 8; j++) {
            int c = n_blk + j * 8 + (lane & 3) * 2;
            #pragma unroll
            for (int h = 0; h < 2; h++) {
                int o = m_blk + i * 16 + (lane >> 2) + h * 8;
                float bv = bias[o];
                float v0 = acc[i][j][h * 2 + 0] + bv;
                float v1 = acc[i][j][h * 2 + 1] + bv;
                if (ACT == 1) { v0 = silu_f(v0); v1 = silu_f(v1); }
                if (OUTFMT != 1) {
                    float* yp = Y + ((size_t)b * CC + o) * S + s0 + c;
                    float w0 = v0, w1 = v1;
                    if (EPI == 1) {
                        const float* ep = extra + ((size_t)b * CC + o) * S + s0 + c;
                        w0 += scl * ep[0]; w1 += scl * ep[1];
                    }
                    if (EPI == 2) { w0 += yp[0]; w1 += yp[1]; }
                    float2 ov; ov.x = w0; ov.y = w1;
                    *(float2*)yp = ov;
                }
                if (OUTFMT >= 1) {
                    trans[c * TP + o] = pack_hl(v0);
                    trans[(c + 1) * TP + o] = pack_hl(v1);
                }
            }
        }
    }
    if (OUTFMT >= 1) {
        __syncthreads();
        u16* thi = tout + tb;
        u16* tlo = thi + 16384;
        #pragma unroll
        for (int it = 0; it < 16; it++) {
            int idx = tid + it * 256;
            int s = idx >> 5, c0 = (idx & 31) * 4;
            uint4 w = *(const uint4*)(trans + s * TP + c0);
            u64 hv = (u64)(w.x & 0xffff) | ((u64)(w.y & 0xffff) << 16)
                   | ((u64)(w.z & 0xffff) << 32) | ((u64)(w.w & 0xffff) << 48);
            u64 lv = (u64)(w.x >> 16) | ((u64)(w.y >> 16) << 16)
                   | ((u64)(w.z >> 16) << 32) | ((u64)(w.w >> 16) << 48);
            *(u64*)(thi + s * 128 + c0) = hv;
            *(u64*)(tlo + s * 128 + c0) = lv;
        }
    }
}

// ================= GLU (fp32 input w/ rms, bf16 tile output) — R7 layout =================
#define GL_AAHI 0
#define GL_AALO (GL_AAHI + TILE_B)
#define GL_AGHI (GL_AALO + TILE_B)
#define GL_AGLO (GL_AGHI + TILE_B)
#define GL_BHI  (GL_AGLO + TILE_B)
#define GL_BLO  (GL_BHI  + TILE_B)
#define GL_SMEM (GL_BLO  + TILE_B)

__global__ __launch_bounds__(256)
void glu_mm(const float* __restrict__ X, const u16* __restrict__ wsc,
            const float* __restrict__ bias, u16* __restrict__ tout,
            const float* __restrict__ rms, int S)
{
    extern __shared__ char sm[];
    u32 sb = smem_u32(sm);
    int tid = threadIdx.x;
    int wid = tid >> 5, lane = tid & 31;
    int b  = blockIdx.y;
    int s0 = blockIdx.x * 128;
    size_t tb = ((size_t)(b * gridDim.x + blockIdx.x)) * 32768;
    const float* Xb = X + (size_t)b * CC * S;

    stage_tile(sb + GL_AAHI, wsc, tid);
    stage_tile(sb + GL_AGHI, wsc + 16384, tid);
    stage_tile(sb + GL_AALO, wsc + 32768, tid);
    stage_tile(sb + GL_AGLO, wsc + 49152, tid);
    CP_COMMIT();
    {
        float rv[4];
        #pragma unroll
        for (int j = 0; j < 4; j++)
            rv[j] = rms[(size_t)b * S + s0 + lane + j * 32];
        #pragma unroll
        for (int i = 0; i < 16; i++) {
            int s = lane + (i & 3) * 32;
            int c0 = ((wid << 2) + (i >> 2)) * 4;
            float4 x4;
            x4.x = Xb[(size_t)(c0 + 0) * S + s0 + s];
            x4.y = Xb[(size_t)(c0 + 1) * S + s0 + s];
            x4.z = Xb[(size_t)(c0 + 2) * S + s0 + s];
            x4.w = Xb[(size_t)(c0 + 3) * S + s0 + s];
            float r = rv[i & 3];
            x4.x *= r; x4.y *= r; x4.z *= r; x4.w *= r;
            cvt_store4(sm, GL_BHI, GL_BLO, s, c0, x4);
        }
    }
    CP_WAIT0();
    __syncthreads();

    int m_blk = (wid & 3) * 32;
    int n_blk = (wid >> 2) * 64;
    float acca[2][8][4], accg[2][8][4];
    #pragma unroll
    for (int i = 0; i < 2; i++)
        #pragma unroll
        for (int j = 0; j < 8; j++)
            #pragma unroll
            for (int q = 0; q < 4; q++) { acca[i][j][q] = 0.f; accg[i][j][q] = 0.f; }

    u32 a_row = (u32)(m_blk + (lane & 15));
    u32 a_koff = (u32)((lane >> 4) << 3);
    u32 b_row = (u32)((lane & 7) + ((lane >> 4) << 3));
    u32 b_koff = (u32)(((lane >> 3) & 1) << 3);

    const u32 aab[3] = {sb + GL_AAHI, sb + GL_AAHI, sb + GL_AALO};
    const u32 agb[3] = {sb + GL_AGHI, sb + GL_AGHI, sb + GL_AGLO};
    const u32 bbb[3] = {sb + GL_BHI,  sb + GL_BLO,  sb + GL_BHI };

    #pragma unroll
    for (int p = 0; p < 3; p++) {
        mm_pass(aab[p], bbb[p], acca, a_row, a_koff, b_row, b_koff, n_blk);
        mm_pass(agb[p], bbb[p], accg, a_row, a_koff, b_row, b_koff, n_blk);
    }

    u32* trans = (u32*)sm;
    __syncthreads();
    #pragma unroll
    for (int i = 0; i < 2; i++) {
        #pragma unroll
        for (int j = 0; j < 8; j++) {
            int c = n_blk + j * 8 + (lane & 3) * 2;
            #pragma unroll
            for (int h = 0; h < 2; h++) {
                int o = m_blk + i * 16 + (lane >> 2) + h * 8;
                float ba = bias[o], bg = bias[CC + o];
                float v0 = (acca[i][j][h * 2 + 0] + ba) * silu_f(accg[i][j][h * 2 + 0] + bg);
                float v1 = (acca[i][j][h * 2 + 1] + ba) * silu_f(accg[i][j][h * 2 + 1] + bg);
                trans[c * TP + o] = pack_hl(v0);
                trans[(c + 1) * TP + o] = pack_hl(v1);
            }
        }
    }
    __syncthreads();
    {
        u16* thi = tout + tb;
        u16* tlo = thi + 16384;
        #pragma unroll
        for (int it = 0; it < 16; it++) {
            int idx = tid + it * 256;
            int s = idx >> 5, c0 = (idx & 31) * 4;
            uint4 w = *(const uint4*)(trans + s * TP + c0);
            u64 hv = (u64)(w.x & 0xffff) | ((u64)(w.y & 0xffff) << 16)
                   | ((u64)(w.z & 0xffff) << 32) | ((u64)(w.w & 0xffff) << 48);
            u64 lv = (u64)(w.x >> 16) | ((u64)(w.y >> 16) << 16)
                   | ((u64)(w.z >> 16) << 32) | ((u64)(w.w >> 16) << 48);
            *(u64*)(thi + s * 128 + c0) = hv;
            *(u64*)(tlo + s * 128 + c0) = lv;
        }
    }
}

// ---------------- Attention (SIMT) ----------------
#define ATT_SMEM_FLOATS (128*72 + 2*64*136)
#define ATT_SMEM_BYTES  (ATT_SMEM_FLOATS * 4)

__global__ __launch_bounds__(256)
void attn_kernel(const float* __restrict__ q, const float* __restrict__ kmat,
                 const float* __restrict__ vmat, const float* __restrict__ basis,
                 const float* __restrict__ ss_p, const float* __restrict__ ps_p,
                 float* __restrict__ att)
{
    extern __shared__ float smf[];
    float* Ks  = smf;
    float* Qs  = smf + 128 * 72;
    float* Vt  = Qs;
    float* Wsm = Qs + 64 * 136;

    int fb = blockIdx.x * 128;
    int t  = blockIdx.y;
    int b  = blockIdx.z;
    int tid = threadIdx.x;
    int tx = tid & 15, ty = tid >> 4;

    const float* kb = kmat + (size_t)b * CC * S_LAT + t * KK;
    #pragma unroll
    for (int it = 0; it < 8; it++) {
        int idx = tid + it * 256;
        int c = idx >> 4, kq = idx & 15;
        float4 v = *(const float4*)(kb + (size_t)c * S_LAT + kq * 4);
        *(float4*)&Ks[c * 72 + kq * 4] = v;
    }
    const float* qb = q + (size_t)b * CC * S_SIDE + t * FF + fb;
    #pragma unroll
    for (int it = 0; it < 16; it++) {
        int idx = tid + it * 256;
        int c = idx >> 5, fq = idx & 31;
        float4 v = *(const float4*)(qb + (size_t)c * S_SIDE + fq * 4);
        *(float4*)&Qs[c * 128 + fq * 4] = v;
    }
    __syncthreads();

    u64 sc2[8][2];
    #pragma unroll
    for (int i = 0; i < 8; i++) { sc2[i][0] = 0ull; sc2[i][1] = 0ull; }

    #pragma unroll 4
    for (int c = 0; c < CC; c++) {
        u64 kp0 = *(const u64*)&Ks[c * 72 + tx * 4];
        u64 kp1 = *(const u64*)&Ks[c * 72 + tx * 4 + 2];
        float4 q0 = *(const float4*)&Qs[c * 128 + ty * 8];
        float4 q1 = *(const float4*)&Qs[c * 128 + ty * 8 + 4];
        u64 qd[8] = {dup2(q0.x),dup2(q0.y),dup2(q0.z),dup2(q0.w),
                     dup2(q1.x),dup2(q1.y),dup2(q1.z),dup2(q1.w)};
        #pragma unroll
        for (int i = 0; i < 8; i++) {
            fma2(sc2[i][0], qd[i], kp0);
            fma2(sc2[i][1], qd[i], kp1);
        }
    }
    float sc[8][4];
    #pragma unroll
    for (int i = 0; i < 8; i++) {
        float2 p0 = unpack2(sc2[i][0]);
        float2 p1 = unpack2(sc2[i][1]);
        sc[i][0] = p0.x; sc[i][1] = p0.y; sc[i][2] = p1.x; sc[i][3] = p1.y;
    }
    float ssv = *ss_p, psv = *ps_p;
    #pragma unroll
    for (int i = 0; i < 8; i++)
        #pragma unroll
        for (int j = 0; j < 4; j++)
            sc[i][j] = sc[i][j] * ssv
                     + basis[(tx * 4 + j) * FF + fb + ty * 8 + i] * psv;
    __syncthreads();

    float w[8][4];
    #pragma unroll
    for (int i = 0; i < 8; i++) {
        float m = fmaxf(fmaxf(sc[i][0], sc[i][1]), fmaxf(sc[i][2], sc[i][3]));
        #pragma unroll
        for (int off = 8; off >= 1; off >>= 1)
            m = fmaxf(m, __shfl_xor_sync(0xffffffffu, m, off));
        float e0 = __expf(sc[i][0] - m);
        float e1 = __expf(sc[i][1] - m);
        float e2 = __expf(sc[i][2] - m);
        float e3 = __expf(sc[i][3] - m);
        float s = e0 + e1 + e2 + e3;
        #pragma unroll
        for (int off = 8; off >= 1; off >>= 1)
            s += __shfl_xor_sync(0xffffffffu, s, off);
        float inv = 1.0f / s;
        w[i][0] = e0 * inv; w[i][1] = e1 * inv;
        w[i][2] = e2 * inv; w[i][3] = e3 * inv;
    }
    #pragma unroll
    for (int i = 0; i < 8; i++)
        #pragma unroll
        for (int j = 0; j < 4; j++)
            Wsm[(tx * 4 + j) * 136 + ty * 8 + i] = w[i][j];

    const float* vb = vmat + (size_t)b * CC * S_LAT + t * KK;
    #pragma unroll
    for (int it = 0; it < 8; it++) {
        int idx = tid + it * 256;
        int c = idx >> 4, kq = idx & 15;
        float4 v = *(const float4*)(vb + (size_t)c * S_LAT + kq * 4);
        Vt[(kq * 4 + 0) * 136 + c] = v.x;
        Vt[(kq * 4 + 1) * 136 + c] = v.y;
        Vt[(kq * 4 + 2) * 136 + c] = v.z;
        Vt[(kq * 4 + 3) * 136 + c] = v.w;
    }
    __syncthreads();

    u64 ac2[4][8];
    #pragma unroll
    for (int i = 0; i < 4; i++)
        #pragma unroll
        for (int j = 0; j < 8; j++) ac2[i][j] = 0ull;

    #pragma unroll 4
    for (int k = 0; k < KK; k++) {
        u64 vp[4];
        #pragma unroll
        for (int i = 0; i < 4; i++)
            vp[i] = *(const u64*)&Vt[k * 136 + ty * 8 + 2 * i];
        float4 w0 = *(const float4*)&Wsm[k * 136 + tx * 8];
        float4 w1 = *(const float4*)&Wsm[k * 136 + tx * 8 + 4];
        u64 wd[8] = {dup2(w0.x),dup2(w0.y),dup2(w0.z),dup2(w0.w),
                     dup2(w1.x),dup2(w1.y),dup2(w1.z),dup2(w1.w)};
        #pragma unroll
        for (int i = 0; i < 4; i++)
            #pragma unroll
            for (int j = 0; j < 8; j++)
                fma2(ac2[i][j], vp[i], wd[j]);
    }
    #pragma unroll
    for (int i = 0; i < 4; i++) {
        float r0[8], r1[8];
        #pragma unroll
        for (int j = 0; j < 8; j++) {
            float2 p = unpack2(ac2[i][j]);
            r0[j] = p.x; r1[j] = p.y;
        }
        #pragma unroll
        for (int half = 0; half < 2; half++) {
            int c = ty * 8 + 2 * i + half;
            float* rr = half ? r1 : r0;
            float* orow = att + (((size_t)b * CC + c) * TT + t) * FF + fb + tx * 8;
            *(float4*)(orow + 0) = make_float4(rr[0], rr[1], rr[2], rr[3]);
            *(float4*)(orow + 4) = make_float4(rr[4], rr[5], rr[6], rr[7]);
        }
    }
}

// ---------------- host ----------------
extern "C" void kernel_launch(void* const* d_in, const int* in_sizes, int n_in,
                              void* d_out, int out_size)
{
    const float* latent     = (const float*)d_in[0];
    const float* side       = (const float*)d_in[1];
    const float* basis      = (const float*)d_in[2];
    const float* lp_gamma   = (const float*)d_in[3];
    const float* lp_w       = (const float*)d_in[4];
    const float* lp_b       = (const float*)d_in[5];
    const float* qn_gamma   = (const float*)d_in[6];
    const float* qmlp_in_w  = (const float*)d_in[7];
    const float* qmlp_in_b  = (const float*)d_in[8];
    const float* qmlp_out_w = (const float*)d_in[9];
    const float* qmlp_out_b = (const float*)d_in[10];
    const float* q_w        = (const float*)d_in[11];
    const float* q_b        = (const float*)d_in[12];
    const float* k_w        = (const float*)d_in[13];
    const float* k_b        = (const float*)d_in[14];
    const float* v_w        = (const float*)d_in[15];
    const float* v_b        = (const float*)d_in[16];
    const float* o_w        = (const float*)d_in[17];
    const float* o_b        = (const float*)d_in[18];
    const float* ffn_gamma  = (const float*)d_in[19];
    const float* ffn_in_w   = (const float*)d_in[20];
    const float* ffn_in_b   = (const float*)d_in[21];
    const float* ffn_out_w  = (const float*)d_in[22];
    const float* ffn_out_b  = (const float*)d_in[23];
    const float* score_sc   = (const float*)d_in[24];
    const float* prior_sc   = (const float*)d_in[25];
    const float* qskip_sc   = (const float*)d_in[26];
    float* out = (float*)d_out;

    float *buf1, *buf2, *buf3, *rmsb, *rmsL, *kmat, *vmat, *qbias;
    u16 *tA, *tL, *wbf;
    cudaGetSymbolAddress((void**)&buf1, g_buf1);
    cudaGetSymbolAddress((void**)&buf2, g_buf2);
    cudaGetSymbolAddress((void**)&buf3, g_buf3);
    cudaGetSymbolAddress((void**)&rmsb, g_rms);
    cudaGetSymbolAddress((void**)&rmsL, g_rmsL);
    cudaGetSymbolAddress((void**)&kmat, g_k);
    cudaGetSymbolAddress((void**)&vmat, g_v);
    cudaGetSymbolAddress((void**)&qbias, g_qbias);
    cudaGetSymbolAddress((void**)&tA,   g_tA);
    cudaGetSymbolAddress((void**)&tL,   g_tL);
    cudaGetSymbolAddress((void**)&wbf,  g_wbf);

    cudaFuncSetAttribute(attn_kernel, cudaFuncAttributeMaxDynamicSharedMemorySize, ATT_SMEM_BYTES);
    cudaFuncSetAttribute(gemm_f32in<1,1,0,1>, cudaFuncAttributeMaxDynamicSharedMemorySize, GT_SMEM);
    cudaFuncSetAttribute(gemm_f32in<0,0,1,0>, cudaFuncAttributeMaxDynamicSharedMemorySize, GT_SMEM);
    cudaFuncSetAttribute(gemm_bf64<0>, cudaFuncAttributeMaxDynamicSharedMemorySize, B64_SMEM);
    cudaFuncSetAttribute(gemm_bf64<2>, cudaFuncAttributeMaxDynamicSharedMemorySize, B64_SMEM);
    cudaFuncSetAttribute(glu_mm, cudaFuncAttributeMaxDynamicSharedMemorySize, GL_SMEM);

    dim3 blk(256);

    // 0: fused weight pre-convert
    convert_all<<<640, blk>>>(lp_w, k_w, v_w, qmlp_out_w, o_w, ffn_out_w,
                              qmlp_in_w, ffn_in_w, lp_gamma, qn_gamma, ffn_gamma, wbf);
    // 1: fold q through qmlp_out
    qfold_prep<<<64, blk>>>(q_w, qmlp_out_w, qmlp_out_b, q_b, wbf + WQ, qbias);

    // 2,3: inv-rms
    rms_scale_kernel<<<dim3(S_LAT/1024, BB), blk>>>(latent, rmsL, S_LAT);
    rms_scale_kernel<<<dim3(S_SIDE/1024, BB), blk>>>(side, rmsb, S_SIDE);

    // 4: latent_pre (fp32 in, tile out)
    gemm_f32in<1,1,0,1><<<dim3(S_LAT/128, BB), blk, GT_SMEM>>>(
        latent, wbf + WLP, lp_b, nullptr, nullptr, nullptr, rmsL, tL, S_LAT);

    // 5: glu1 — PROFILED SLOT
    glu_mm<<<dim3(S_SIDE/128, BB), blk, GL_SMEM>>>(side, wbf + WQI, qmlp_in_b, tA, rmsb, S_SIDE);

    // 6: qmlp_out -> buf3 (fp32 only; tile no longer needed thanks to q-fold)
    gemm_bf64<0><<<dim3(S_SIDE/64, BB), blk, B64_SMEM>>>(
        wbf + WQO, qmlp_out_b, tA, buf3, S_SIDE);

    // 7: q (folded weights, reads tA)
    gemm_bf64<0><<<dim3(S_SIDE/64, BB), blk, B64_SMEM>>>(
        wbf + WQ, qbias, tA, buf2, S_SIDE);

    // 8,9: k, v
    gemm_bf64<0><<<dim3(S_LAT/64, BB), blk, B64_SMEM>>>(
        wbf + WK, k_b, tL, kmat, S_LAT);
    gemm_bf64<0><<<dim3(S_LAT/64, BB), blk, B64_SMEM>>>(
        wbf + WV, v_b, tL, vmat, S_LAT);

    // 10: attention
    attn_kernel<<<dim3(FF/128, TT, BB), blk, ATT_SMEM_BYTES>>>(
        buf2, kmat, vmat, basis, score_sc, prior_sc, buf1);

    // 11: o-proj + query skip
    gemm_f32in<0,0,1,0><<<dim3(S_SIDE/128, BB), blk, GT_SMEM>>>(
        buf1, wbf + WO, o_b, out, buf3, qskip_sc, nullptr, nullptr, S_SIDE);

    // 12,13,14: FFN
    rms_scale_kernel<<<dim3(S_SIDE/1024, BB), blk>>>(out, rmsb, S_SIDE);
    glu_mm<<<dim3(S_SIDE/128, BB), blk, GL_SMEM>>>(out, wbf + WFI, ffn_in_b, tA, rmsb, S_SIDE);
    gemm_bf64<2><<<dim3(S_SIDE/64, BB), blk, B64_SMEM>>>(
        wbf + WFO, ffn_out_b, tA, out, S_SIDE);
}

// round 12
// speedup vs baseline: 2.3584x; 1.7602x over previous
#include <cuda_runtime.h>
#include <cuda_fp16.h>
#include <cstdint>

#define BB 8
#define CC 128
#define TT 128
#define FF 512
#define KK 64
#define S_SIDE (TT*FF)
#define S_LAT  (TT*KK)

typedef unsigned long long u64;
typedef unsigned int u32;
typedef unsigned short u16;

// ---------------- scratch ----------------
__device__ float g_buf1[BB*CC*S_SIDE];            // attention out
__device__ float g_buf2[BB*CC*S_SIDE];            // q (fp32)
__device__ float g_buf3[BB*CC*S_SIDE];            // query_h (fp32, for skip)
__device__ float g_rms [BB*S_SIDE];               // side/ffn inv-rms
__device__ float g_rmsL[BB*S_LAT];                // latent inv-rms
__device__ float g_k  [BB*CC*S_LAT];
__device__ float g_v  [BB*CC*S_LAT];
__device__ float g_qbias[CC];                     // folded q bias

// fp16 tile buffers: per (b,tile128): 16384 u16
__device__ u16 g_tA[8*512*16384];                 // glu1 out / glu2 out
__device__ u16 g_tL[8*64*16384];                  // latent_h

// pre-converted fp16 weights
#define WLP 0
#define WK  16384
#define WV  32768
#define WQO 49152
#define WO  65536
#define WFO 81920
#define WQI 98304
#define WFI 131072
__device__ u16 g_wbf[163840];
__device__ u16 g_wq[16384];                       // folded q weights (fp16)

__device__ __forceinline__ float silu_f(float x) { return x / (1.0f + __expf(-x)); }
__device__ __forceinline__ u64 dup2(float v) {
    u64 r; asm("mov.b64 %0, {%1, %2};" : "=l"(r) : "f"(v), "f"(v)); return r;
}
__device__ __forceinline__ void fma2(u64& d, u64 a, u64 b) {
    asm("fma.rn.f32x2 %0, %1, %2, %0;" : "+l"(d) : "l"(a), "l"(b));
}
__device__ __forceinline__ float2 unpack2(u64 v) {
    float2 r; asm("mov.b64 {%0, %1}, %2;" : "=f"(r.x), "=f"(r.y) : "l"(v)); return r;
}
__device__ __forceinline__ u32 smem_u32(const void* p) {
    u32 a;
    asm("{ .reg .u64 t; cvta.to.shared.u64 t, %1; cvt.u32.u64 %0, t; }" : "=r"(a) : "l"(p));
    return a;
}

// ---------------- mma.sync helpers (fp16) ----------------
__device__ __forceinline__ void ldsm4(u32* r, u32 addr) {
    asm volatile("ldmatrix.sync.aligned.m8n8.x4.shared.b16 {%0,%1,%2,%3}, [%4];"
                 : "=r"(r[0]), "=r"(r[1]), "=r"(r[2]), "=r"(r[3]) : "r"(addr));
}
__device__ __forceinline__ void mma16816(float* d, const u32* a, const u32* b) {
    asm volatile("mma.sync.aligned.m16n8k16.row.col.f32.f16.f16.f32 "
                 "{%0,%1,%2,%3}, {%4,%5,%6,%7}, {%8,%9}, {%0,%1,%2,%3};"
                 : "+f"(d[0]), "+f"(d[1]), "+f"(d[2]), "+f"(d[3])
                 : "r"(a[0]), "r"(a[1]), "r"(a[2]), "r"(a[3]), "r"(b[0]), "r"(b[1]));
}
__device__ __forceinline__ void cpa16(u32 saddr, const void* g) {
    asm volatile("cp.async.cg.shared.global [%0], [%1], 16;" :: "r"(saddr), "l"(g));
}
#define CP_COMMIT() asm volatile("cp.async.commit_group;" ::: "memory")
#define CP_WAIT0()  asm volatile("cp.async.wait_group 0;" ::: "memory")

#define TSTR  272
#define TILE_B (128*TSTR)
#define TPH 136

// fp32x4 -> fp16x4 store into padded smem tile
__device__ __forceinline__ void cvt_store4h(char* smem, u32 base, int row, int col, float4 x) {
    __half h0 = __float2half_rn(x.x);
    __half h1 = __float2half_rn(x.y);
    __half h2 = __float2half_rn(x.z);
    __half h3 = __float2half_rn(x.w);
    u64 hv = (u64)*(u16*)&h0 | ((u64)*(u16*)&h1 << 16) | ((u64)*(u16*)&h2 << 32) | ((u64)*(u16*)&h3 << 48);
    *(u64*)(smem + base + (u32)(row * TSTR + col * 2)) = hv;
}

// stage one contiguous 128x128 u16 tile into TSTR-padded smem via cp.async
__device__ __forceinline__ void stage_tile(u32 sbase, const u16* g, int tid) {
    #pragma unroll
    for (int it = 0; it < 8; it++) {
        int idx = tid + it * 256;
        int r = idx >> 4, ch = idx & 15;
        cpa16(sbase + r * TSTR + ch * 16, g + r * 128 + ch * 8);
    }
}

// one k=128 HMMA pass; warp covers 32m x 64n
__device__ __forceinline__ void mm_pass(u32 ab, u32 bb, float (*acc)[8][4],
                                        u32 a_row, u32 a_koff, u32 b_row, u32 b_koff,
                                        int n_blk)
{
    #pragma unroll
    for (int ks = 0; ks < 8; ks++) {
        int k0 = ks * 16;
        u32 af[2][4], bf[4][4];
        #pragma unroll
        for (int i = 0; i < 2; i++)
            ldsm4(af[i], ab + (a_row + i * 16) * TSTR + (k0 + a_koff) * 2);
        #pragma unroll
        for (int j = 0; j < 4; j++)
            ldsm4(bf[j], bb + (n_blk + j * 16 + b_row) * TSTR + (k0 + b_koff) * 2);
        #pragma unroll
        for (int i = 0; i < 2; i++)
            #pragma unroll
            for (int j = 0; j < 8; j++)
                mma16816(acc[i][j], af[i], &bf[j >> 1][(j & 1) * 2]);
    }
}

// ---------------- fused weight pre-convert (gamma folded, fp16) ----------------
__global__ __launch_bounds__(256)
void convert_all(const float* __restrict__ lp_w, const float* __restrict__ k_w,
                 const float* __restrict__ v_w,  const float* __restrict__ qo_w,
                 const float* __restrict__ o_w,  const float* __restrict__ fo_w,
                 const float* __restrict__ qi_w, const float* __restrict__ fi_w,
                 const float* __restrict__ lp_g, const float* __restrict__ qn_g,
                 const float* __restrict__ ffn_g, u16* __restrict__ dst)
{
    int bid = blockIdx.x;
    const float* src; const float* gamma = nullptr; int off, n, lb;
    if (bid < 384) {
        int seg = bid >> 6; lb = bid & 63; n = 16384;
        switch (seg) {
            case 0: src = lp_w; gamma = lp_g; off = WLP; break;
            case 1: src = k_w;  off = WK;  break;
            case 2: src = v_w;  off = WV;  break;
            case 3: src = qo_w; off = WQO; break;
            case 4: src = o_w;  off = WO;  break;
            default: src = fo_w; off = WFO; break;
        }
    } else if (bid < 512) {
        lb = bid - 384; src = qi_w; gamma = qn_g; off = WQI; n = 32768;
    } else {
        lb = bid - 512; src = fi_w; gamma = ffn_g; off = WFI; n = 32768;
    }
    int idx = lb * 256 + threadIdx.x;
    if (idx >= n) return;
    float v = src[idx];
    if (gamma) v *= gamma[idx & 127];
    __half h = __float2half_rn(v);
    dst[off + idx] = *(u16*)&h;
}

// ---------------- fold q through qmlp_out ----------------
__global__ __launch_bounds__(256)
void qfold_prep(const float* __restrict__ qw, const float* __restrict__ qow,
                const float* __restrict__ qob, const float* __restrict__ qb,
                u16* __restrict__ dst, float* __restrict__ qbias)
{
    int idx = blockIdx.x * 256 + threadIdx.x;   // 0..16383
    int o = idx >> 7, c = idx & 127;
    float s = 0.f;
    #pragma unroll 4
    for (int m = 0; m < 128; m++)
        s += qw[o * 128 + m] * qow[m * 128 + c];
    __half h = __float2half_rn(s);
    dst[idx] = *(u16*)&h;
    if (c == 0) {
        float t = qb[o];
        #pragma unroll 4
        for (int m = 0; m < 128; m++)
            t += qw[o * 128 + m] * qob[m];
        qbias[o] = t;
    }
}

// ---------------- inv-RMS ----------------
__global__ __launch_bounds__(256)
void rms_scale_kernel(const float* __restrict__ X, float* __restrict__ R, int S)
{
    int b = blockIdx.y;
    int s = blockIdx.x * 1024 + threadIdx.x * 4;
    const float* xb = X + (size_t)b * CC * S + s;
    float4 acc = make_float4(0.f, 0.f, 0.f, 0.f);
    #pragma unroll 4
    for (int c = 0; c < CC; c++) {
        float4 v = *(const float4*)(xb + (size_t)c * S);
        acc.x += v.x * v.x; acc.y += v.y * v.y;
        acc.z += v.z * v.z; acc.w += v.w * v.w;
    }
    const float inv = 1.0f / CC;
    float4 r;
    r.x = rsqrtf(acc.x * inv + 1e-6f);
    r.y = rsqrtf(acc.y * inv + 1e-6f);
    r.z = rsqrtf(acc.z * inv + 1e-6f);
    r.w = rsqrtf(acc.w * inv + 1e-6f);
    *(float4*)(R + (size_t)b * S + s) = r;
}

// ================= fp16 single-pass GEMM, tile input (2 CTAs/SM) =================
#define T16_A 0
#define T16_B TILE_B
#define T16_SMEM (2*TILE_B)

// EPI: 0 none, 2 += Y
template<int EPI>
__global__ __launch_bounds__(256, 2)
void gemm_t16(const u16* __restrict__ wsc, const float* __restrict__ bias,
              const u16* __restrict__ tin, float* __restrict__ Y, int S)
{
    extern __shared__ char sm[];
    u32 sb = smem_u32(sm);
    int tid = threadIdx.x;
    int wid = tid >> 5, lane = tid & 31;
    int b  = blockIdx.y;
    int s0 = blockIdx.x * 128;
    size_t tb = ((size_t)(b * gridDim.x + blockIdx.x)) * 16384;

    stage_tile(sb + T16_A, wsc, tid);
    stage_tile(sb + T16_B, tin + tb, tid);
    CP_COMMIT();

    int m_blk = (wid & 3) * 32;
    int n_blk = (wid >> 2) * 64;
    float acc[2][8][4];
    #pragma unroll
    for (int i = 0; i < 2; i++)
        #pragma unroll
        for (int j = 0; j < 8; j++)
            #pragma unroll
            for (int q = 0; q < 4; q++) acc[i][j][q] = 0.f;

    u32 a_row = (u32)(m_blk + (lane & 15));
    u32 a_koff = (u32)((lane >> 4) << 3);
    u32 b_row = (u32)((lane & 7) + ((lane >> 4) << 3));
    u32 b_koff = (u32)(((lane >> 3) & 1) << 3);

    CP_WAIT0(); __syncthreads();
    mm_pass(sb + T16_A, sb + T16_B, acc, a_row, a_koff, b_row, b_koff, n_blk);

    #pragma unroll
    for (int i = 0; i < 2; i++) {
        #pragma unroll
        for (int j = 0; j < 8; j++) {
            int c = n_blk + j * 8 + (lane & 3) * 2;
            #pragma unroll
            for (int h = 0; h < 2; h++) {
                int o = m_blk + i * 16 + (lane >> 2) + h * 8;
                float bv = bias[o];
                float v0 = acc[i][j][h * 2 + 0] + bv;
                float v1 = acc[i][j][h * 2 + 1] + bv;
                float* yp = Y + ((size_t)b * CC + o) * S + s0 + c;
                if (EPI == 2) { v0 += yp[0]; v1 += yp[1]; }
                float2 ov; ov.x = v0; ov.y = v1;
                *(float2*)yp = ov;
            }
        }
    }
}

// ================= fp16 single-pass GEMM, fp32 input =================
// NORM: X *= rms[s]; ACT: silu; EPI: 0 none, 1 +scl*extra; OUTFMT: 0 fp32, 1 tile
template<int NORM, int ACT, int EPI, int OUTFMT>
__global__ __launch_bounds__(256, 2)
void gemm_f16in(const float* __restrict__ X, const u16* __restrict__ wsc,
                const float* __restrict__ bias, float* __restrict__ Y,
                const float* __restrict__ extra, const float* __restrict__ sc_p,
                const float* __restrict__ rms, u16* __restrict__ tout, int S)
{
    extern __shared__ char sm[];
    u32 sb = smem_u32(sm);
    int tid = threadIdx.x;
    int wid = tid >> 5, lane = tid & 31;
    int b  = blockIdx.y;
    int s0 = blockIdx.x * 128;
    size_t tb = ((size_t)(b * gridDim.x + blockIdx.x)) * 16384;
    const float* Xb = X + (size_t)b * CC * S;

    stage_tile(sb + T16_A, wsc, tid);
    CP_COMMIT();
    {
        float rv[4];
        #pragma unroll
        for (int j = 0; j < 4; j++)
            rv[j] = NORM ? rms[(size_t)b * S + s0 + lane + j * 32] : 1.0f;
        #pragma unroll
        for (int i = 0; i < 16; i++) {
            int s = lane + (i & 3) * 32;
            int c0 = ((wid << 2) + (i >> 2)) * 4;
            float4 x4;
            x4.x = Xb[(size_t)(c0 + 0) * S + s0 + s];
            x4.y = Xb[(size_t)(c0 + 1) * S + s0 + s];
            x4.z = Xb[(size_t)(c0 + 2) * S + s0 + s];
            x4.w = Xb[(size_t)(c0 + 3) * S + s0 + s];
            if (NORM) {
                float r = rv[i & 3];
                x4.x *= r; x4.y *= r; x4.z *= r; x4.w *= r;
            }
            cvt_store4h(sm, T16_B, s, c0, x4);
        }
    }

    int m_blk = (wid & 3) * 32;
    int n_blk = (wid >> 2) * 64;
    float acc[2][8][4];
    #pragma unroll
    for (int i = 0; i < 2; i++)
        #pragma unroll
        for (int j = 0; j < 8; j++)
            #pragma unroll
            for (int q = 0; q < 4; q++) acc[i][j][q] = 0.f;

    u32 a_row = (u32)(m_blk + (lane & 15));
    u32 a_koff = (u32)((lane >> 4) << 3);
    u32 b_row = (u32)((lane & 7) + ((lane >> 4) << 3));
    u32 b_koff = (u32)(((lane >> 3) & 1) << 3);

    CP_WAIT0(); __syncthreads();
    mm_pass(sb + T16_A, sb + T16_B, acc, a_row, a_koff, b_row, b_koff, n_blk);

    float scl = (EPI == 1) ? *sc_p : 0.f;
    u16* trans = (u16*)(sm + T16_B);
    if (OUTFMT == 1) __syncthreads();
    #pragma unroll
    for (int i = 0; i < 2; i++) {
        #pragma unroll
        for (int j = 0; j < 8; j++) {
            int c = n_blk + j * 8 + (lane & 3) * 2;
            #pragma unroll
            for (int h = 0; h < 2; h++) {
                int o = m_blk + i * 16 + (lane >> 2) + h * 8;
                float bv = bias[o];
                float v0 = acc[i][j][h * 2 + 0] + bv;
                float v1 = acc[i][j][h * 2 + 1] + bv;
                if (ACT == 1) { v0 = silu_f(v0); v1 = silu_f(v1); }
                if (OUTFMT == 0) {
                    float* yp = Y + ((size_t)b * CC + o) * S + s0 + c;
                    float w0 = v0, w1 = v1;
                    if (EPI == 1) {
                        const float* ep = extra + ((size_t)b * CC + o) * S + s0 + c;
                        w0 += scl * ep[0]; w1 += scl * ep[1];
                    }
                    float2 ov; ov.x = w0; ov.y = w1;
                    *(float2*)yp = ov;
                } else {
                    __half q0 = __float2half_rn(v0);
                    __half q1 = __float2half_rn(v1);
                    trans[c * TPH + o] = *(u16*)&q0;
                    trans[(c + 1) * TPH + o] = *(u16*)&q1;
                }
            }
        }
    }
    if (OUTFMT == 1) {
        __syncthreads();
        u16* thi = tout + tb;
        #pragma unroll
        for (int it = 0; it < 8; it++) {
            int idx = tid + it * 256;
            int s = idx >> 4, c0 = (idx & 15) * 8;
            uint4 w = *(const uint4*)(trans + s * TPH + c0);
            *(uint4*)(thi + s * 128 + c0) = w;
        }
    }
}

// ================= fp16 single-pass GLU =================
#define GL_AA 0
#define GL_AG TILE_B
#define GL_B  (2*TILE_B)
#define GL_SMEM (3*TILE_B)

__global__ __launch_bounds__(256)
void glu_f16(const float* __restrict__ X, const u16* __restrict__ wsc,
             const float* __restrict__ bias, u16* __restrict__ tout,
             const float* __restrict__ rms, int S)
{
    extern __shared__ char sm[];
    u32 sb = smem_u32(sm);
    int tid = threadIdx.x;
    int wid = tid >> 5, lane = tid & 31;
    int b  = blockIdx.y;
    int s0 = blockIdx.x * 128;
    size_t tb = ((size_t)(b * gridDim.x + blockIdx.x)) * 16384;
    const float* Xb = X + (size_t)b * CC * S;

    stage_tile(sb + GL_AA, wsc, tid);
    stage_tile(sb + GL_AG, wsc + 16384, tid);
    CP_COMMIT();
    {
        float rv[4];
        #pragma unroll
        for (int j = 0; j < 4; j++)
            rv[j] = rms[(size_t)b * S + s0 + lane + j * 32];
        #pragma unroll
        for (int i = 0; i < 16; i++) {
            int s = lane + (i & 3) * 32;
            int c0 = ((wid << 2) + (i >> 2)) * 4;
            float4 x4;
            x4.x = Xb[(size_t)(c0 + 0) * S + s0 + s];
            x4.y = Xb[(size_t)(c0 + 1) * S + s0 + s];
            x4.z = Xb[(size_t)(c0 + 2) * S + s0 + s];
            x4.w = Xb[(size_t)(c0 + 3) * S + s0 + s];
            float r = rv[i & 3];
            x4.x *= r; x4.y *= r; x4.z *= r; x4.w *= r;
            cvt_store4h(sm, GL_B, s, c0, x4);
        }
    }
    CP_WAIT0();
    __syncthreads();

    int m_blk = (wid & 3) * 32;
    int n_blk = (wid >> 2) * 64;
    float acca[2][8][4], accg[2][8][4];
    #pragma unroll
    for (int i = 0; i < 2; i++)
        #pragma unroll
        for (int j = 0; j < 8; j++)
            #pragma unroll
            for (int q = 0; q < 4; q++) { acca[i][j][q] = 0.f; accg[i][j][q] = 0.f; }

    u32 a_row = (u32)(m_blk + (lane & 15));
    u32 a_koff = (u32)((lane >> 4) << 3);
    u32 b_row = (u32)((lane & 7) + ((lane >> 4) << 3));
    u32 b_koff = (u32)(((lane >> 3) & 1) << 3);

    mm_pass(sb + GL_AA, sb + GL_B, acca, a_row, a_koff, b_row, b_koff, n_blk);
    mm_pass(sb + GL_AG, sb + GL_B, accg, a_row, a_koff, b_row, b_koff, n_blk);

    u16* trans = (u16*)sm;
    __syncthreads();
    #pragma unroll
    for (int i = 0; i < 2; i++) {
        #pragma unroll
        for (int j = 0; j < 8; j++) {
            int c = n_blk + j * 8 + (lane & 3) * 2;
            #pragma unroll
            for (int h = 0; h < 2; h++) {
                int o = m_blk + i * 16 + (lane >> 2) + h * 8;
                float ba = bias[o], bg = bias[CC + o];
                float v0 = (acca[i][j][h * 2 + 0] + ba) * silu_f(accg[i][j][h * 2 + 0] + bg);
                float v1 = (acca[i][j][h * 2 + 1] + ba) * silu_f(accg[i][j][h * 2 + 1] + bg);
                __half q0 = __float2half_rn(v0);
                __half q1 = __float2half_rn(v1);
                trans[c * TPH + o] = *(u16*)&q0;
                trans[(c + 1) * TPH + o] = *(u16*)&q1;
            }
        }
    }
    __syncthreads();
    {
        u16* thi = tout + tb;
        #pragma unroll
        for (int it = 0; it < 8; it++) {
            int idx = tid + it * 256;
            int s = idx >> 4, c0 = (idx & 15) * 8;
            uint4 w = *(const uint4*)(trans + s * TPH + c0);
            *(uint4*)(thi + s * 128 + c0) = w;
        }
    }
}

// ---------------- Attention (SIMT fp32, unchanged) ----------------
#define ATT_SMEM_FLOATS (128*72 + 2*64*136)
#define ATT_SMEM_BYTES  (ATT_SMEM_FLOATS * 4)

__global__ __launch_bounds__(256)
void attn_kernel(const float* __restrict__ q, const float* __restrict__ kmat,
                 const float* __restrict__ vmat, const float* __restrict__ basis,
                 const float* __restrict__ ss_p, const float* __restrict__ ps_p,
                 float* __restrict__ att)
{
    extern __shared__ float smf[];
    float* Ks  = smf;
    float* Qs  = smf + 128 * 72;
    float* Vt  = Qs;
    float* Wsm = Qs + 64 * 136;

    int fb = blockIdx.x * 128;
    int t  = blockIdx.y;
    int b  = blockIdx.z;
    int tid = threadIdx.x;
    int tx = tid & 15, ty = tid >> 4;

    const float* kb = kmat + (size_t)b * CC * S_LAT + t * KK;
    #pragma unroll
    for (int it = 0; it < 8; it++) {
        int idx = tid + it * 256;
        int c = idx >> 4, kq = idx & 15;
        float4 v = *(const float4*)(kb + (size_t)c * S_LAT + kq * 4);
        *(float4*)&Ks[c * 72 + kq * 4] = v;
    }
    const float* qb = q + (size_t)b * CC * S_SIDE + t * FF + fb;
    #pragma unroll
    for (int it = 0; it < 16; it++) {
        int idx = tid + it * 256;
        int c = idx >> 5, fq = idx & 31;
        float4 v = *(const float4*)(qb + (size_t)c * S_SIDE + fq * 4);
        *(float4*)&Qs[c * 128 + fq * 4] = v;
    }
    __syncthreads();

    u64 sc2[8][2];
    #pragma unroll
    for (int i = 0; i < 8; i++) { sc2[i][0] = 0ull; sc2[i][1] = 0ull; }

    #pragma unroll 4
    for (int c = 0; c < CC; c++) {
        u64 kp0 = *(const u64*)&Ks[c * 72 + tx * 4];
        u64 kp1 = *(const u64*)&Ks[c * 72 + tx * 4 + 2];
        float4 q0 = *(const float4*)&Qs[c * 128 + ty * 8];
        float4 q1 = *(const float4*)&Qs[c * 128 + ty * 8 + 4];
        u64 qd[8] = {dup2(q0.x),dup2(q0.y),dup2(q0.z),dup2(q0.w),
                     dup2(q1.x),dup2(q1.y),dup2(q1.z),dup2(q1.w)};
        #pragma unroll
        for (int i = 0; i < 8; i++) {
            fma2(sc2[i][0], qd[i], kp0);
            fma2(sc2[i][1], qd[i], kp1);
        }
    }
    float sc[8][4];
    #pragma unroll
    for (int i = 0; i < 8; i++) {
        float2 p0 = unpack2(sc2[i][0]);
        float2 p1 = unpack2(sc2[i][1]);
        sc[i][0] = p0.x; sc[i][1] = p0.y; sc[i][2] = p1.x; sc[i][3] = p1.y;
    }
    float ssv = *ss_p, psv = *ps_p;
    #pragma unroll
    for (int i = 0; i < 8; i++)
        #pragma unroll
        for (int j = 0; j < 4; j++)
            sc[i][j] = sc[i][j] * ssv
                     + basis[(tx * 4 + j) * FF + fb + ty * 8 + i] * psv;
    __syncthreads();

    float w[8][4];
    #pragma unroll
    for (int i = 0; i < 8; i++) {
        float m = fmaxf(fmaxf(sc[i][0], sc[i][1]), fmaxf(sc[i][2], sc[i][3]));
        #pragma unroll
        for (int off = 8; off >= 1; off >>= 1)
            m = fmaxf(m, __shfl_xor_sync(0xffffffffu, m, off));
        float e0 = __expf(sc[i][0] - m);
        float e1 = __expf(sc[i][1] - m);
        float e2 = __expf(sc[i][2] - m);
        float e3 = __expf(sc[i][3] - m);
        float s = e0 + e1 + e2 + e3;
        #pragma unroll
        for (int off = 8; off >= 1; off >>= 1)
            s += __shfl_xor_sync(0xffffffffu, s, off);
        float inv = 1.0f / s;
        w[i][0] = e0 * inv; w[i][1] = e1 * inv;
        w[i][2] = e2 * inv; w[i][3] = e3 * inv;
    }
    #pragma unroll
    for (int i = 0; i < 8; i++)
        #pragma unroll
        for (int j = 0; j < 4; j++)
            Wsm[(tx * 4 + j) * 136 + ty * 8 + i] = w[i][j];

    const float* vb = vmat + (size_t)b * CC * S_LAT + t * KK;
    #pragma unroll
    for (int it = 0; it < 8; it++) {
        int idx = tid + it * 256;
        int c = idx >> 4, kq = idx & 15;
        float4 v = *(const float4*)(vb + (size_t)c * S_LAT + kq * 4);
        Vt[(kq * 4 + 0) * 136 + c] = v.x;
        Vt[(kq * 4 + 1) * 136 + c] = v.y;
        Vt[(kq * 4 + 2) * 136 + c] = v.z;
        Vt[(kq * 4 + 3) * 136 + c] = v.w;
    }
    __syncthreads();

    u64 ac2[4][8];
    #pragma unroll
    for (int i = 0; i < 4; i++)
        #pragma unroll
        for (int j = 0; j < 8; j++) ac2[i][j] = 0ull;

    #pragma unroll 4
    for (int k = 0; k < KK; k++) {
        u64 vp[4];
        #pragma unroll
        for (int i = 0; i < 4; i++)
            vp[i] = *(const u64*)&Vt[k * 136 + ty * 8 + 2 * i];
        float4 w0 = *(const float4*)&Wsm[k * 136 + tx * 8];
        float4 w1 = *(const float4*)&Wsm[k * 136 + tx * 8 + 4];
        u64 wd[8] = {dup2(w0.x),dup2(w0.y),dup2(w0.z),dup2(w0.w),
                     dup2(w1.x),dup2(w1.y),dup2(w1.z),dup2(w1.w)};
        #pragma unroll
        for (int i = 0; i < 4; i++)
            #pragma unroll
            for (int j = 0; j < 8; j++)
                fma2(ac2[i][j], vp[i], wd[j]);
    }
    #pragma unroll
    for (int i = 0; i < 4; i++) {
        float r0[8], r1[8];
        #pragma unroll
        for (int j = 0; j < 8; j++) {
            float2 p = unpack2(ac2[i][j]);
            r0[j] = p.x; r1[j] = p.y;
        }
        #pragma unroll
        for (int half = 0; half < 2; half++) {
            int c = ty * 8 + 2 * i + half;
            float* rr = half ? r1 : r0;
            float* orow = att + (((size_t)b * CC + c) * TT + t) * FF + fb + tx * 8;
            *(float4*)(orow + 0) = make_float4(rr[0], rr[1], rr[2], rr[3]);
            *(float4*)(orow + 4) = make_float4(rr[4], rr[5], rr[6], rr[7]);
        }
    }
}

// ---------------- host ----------------
extern "C" void kernel_launch(void* const* d_in, const int* in_sizes, int n_in,
                              void* d_out, int out_size)
{
    const float* latent     = (const float*)d_in[0];
    const float* side       = (const float*)d_in[1];
    const float* basis      = (const float*)d_in[2];
    const float* lp_gamma   = (const float*)d_in[3];
    const float* lp_w       = (const float*)d_in[4];
    const float* lp_b       = (const float*)d_in[5];
    const float* qn_gamma   = (const float*)d_in[6];
    const float* qmlp_in_w  = (const float*)d_in[7];
    const float* qmlp_in_b  = (const float*)d_in[8];
    const float* qmlp_out_w = (const float*)d_in[9];
    const float* qmlp_out_b = (const float*)d_in[10];
    const float* q_w        = (const float*)d_in[11];
    const float* q_b        = (const float*)d_in[12];
    const float* k_w        = (const float*)d_in[13];
    const float* k_b        = (const float*)d_in[14];
    const float* v_w        = (const float*)d_in[15];
    const float* v_b        = (const float*)d_in[16];
    const float* o_w        = (const float*)d_in[17];
    const float* o_b        = (const float*)d_in[18];
    const float* ffn_gamma  = (const float*)d_in[19];
    const float* ffn_in_w   = (const float*)d_in[20];
    const float* ffn_in_b   = (const float*)d_in[21];
    const float* ffn_out_w  = (const float*)d_in[22];
    const float* ffn_out_b  = (const float*)d_in[23];
    const float* score_sc   = (const float*)d_in[24];
    const float* prior_sc   = (const float*)d_in[25];
    const float* qskip_sc   = (const float*)d_in[26];
    float* out = (float*)d_out;

    float *buf1, *buf2, *buf3, *rmsb, *rmsL, *kmat, *vmat, *qbias;
    u16 *tA, *tL, *wbf, *wq;
    cudaGetSymbolAddress((void**)&buf1, g_buf1);
    cudaGetSymbolAddress((void**)&buf2, g_buf2);
    cudaGetSymbolAddress((void**)&buf3, g_buf3);
    cudaGetSymbolAddress((void**)&rmsb, g_rms);
    cudaGetSymbolAddress((void**)&rmsL, g_rmsL);
    cudaGetSymbolAddress((void**)&kmat, g_k);
    cudaGetSymbolAddress((void**)&vmat, g_v);
    cudaGetSymbolAddress((void**)&qbias, g_qbias);
    cudaGetSymbolAddress((void**)&tA,   g_tA);
    cudaGetSymbolAddress((void**)&tL,   g_tL);
    cudaGetSymbolAddress((void**)&wbf,  g_wbf);
    cudaGetSymbolAddress((void**)&wq,   g_wq);

    cudaFuncSetAttribute(attn_kernel, cudaFuncAttributeMaxDynamicSharedMemorySize, ATT_SMEM_BYTES);
    cudaFuncSetAttribute(gemm_f16in<1,1,0,1>, cudaFuncAttributeMaxDynamicSharedMemorySize, T16_SMEM);
    cudaFuncSetAttribute(gemm_f16in<0,0,1,0>, cudaFuncAttributeMaxDynamicSharedMemorySize, T16_SMEM);
    cudaFuncSetAttribute(gemm_t16<0>, cudaFuncAttributeMaxDynamicSharedMemorySize, T16_SMEM);
    cudaFuncSetAttribute(gemm_t16<2>, cudaFuncAttributeMaxDynamicSharedMemorySize, T16_SMEM);
    cudaFuncSetAttribute(glu_f16, cudaFuncAttributeMaxDynamicSharedMemorySize, GL_SMEM);

    dim3 blk(256);

    // 0: fused weight pre-convert
    convert_all<<<640, blk>>>(lp_w, k_w, v_w, qmlp_out_w, o_w, ffn_out_w,
                              qmlp_in_w, ffn_in_w, lp_gamma, qn_gamma, ffn_gamma, wbf);
    // 1: fold q through qmlp_out
    qfold_prep<<<64, blk>>>(q_w, qmlp_out_w, qmlp_out_b, q_b, wq, qbias);

    // 2,3: inv-rms
    rms_scale_kernel<<<dim3(S_LAT/1024, BB), blk>>>(latent, rmsL, S_LAT);
    rms_scale_kernel<<<dim3(S_SIDE/1024, BB), blk>>>(side, rmsb, S_SIDE);

    // 4: latent_pre (fp32 in, tile out)
    gemm_f16in<1,1,0,1><<<dim3(S_LAT/128, BB), blk, T16_SMEM>>>(
        latent, wbf + WLP, lp_b, nullptr, nullptr, nullptr, rmsL, tL, S_LAT);

    // 5: glu1 — PROFILED SLOT
    glu_f16<<<dim3(S_SIDE/128, BB), blk, GL_SMEM>>>(side, wbf + WQI, qmlp_in_b, tA, rmsb, S_SIDE);

    // 6: qmlp_out -> buf3 (fp32; q is folded so no tile needed)
    gemm_t16<0><<<dim3(S_SIDE/128, BB), blk, T16_SMEM>>>(
        wbf + WQO, qmlp_out_b, tA, buf3, S_SIDE);

    // 7: q (folded weights, reads tA)
    gemm_t16<0><<<dim3(S_SIDE/128, BB), blk, T16_SMEM>>>(
        wq, qbias, tA, buf2, S_SIDE);

    // 8,9: k, v
    gemm_t16<0><<<dim3(S_LAT/128, BB), blk, T16_SMEM>>>(
        wbf + WK, k_b, tL, kmat, S_LAT);
    gemm_t16<0><<<dim3(S_LAT/128, BB), blk, T16_SMEM>>>(
        wbf + WV, v_b, tL, vmat, S_LAT);

    // 10: attention
    attn_kernel<<<dim3(FF/128, TT, BB), blk, ATT_SMEM_BYTES>>>(
        buf2, kmat, vmat, basis, score_sc, prior_sc, buf1);

    // 11: o-proj + query skip
    gemm_f16in<0,0,1,0><<<dim3(S_SIDE/128, BB), blk, T16_SMEM>>>(
        buf1, wbf + WO, o_b, out, buf3, qskip_sc, nullptr, nullptr, S_SIDE);

    // 12,13,14: FFN
    rms_scale_kernel<<<dim3(S_SIDE/1024, BB), blk>>>(out, rmsb, S_SIDE);
    glu_f16<<<dim3(S_SIDE/128, BB), blk, GL_SMEM>>>(out, wbf + WFI, ffn_in_b, tA, rmsb, S_SIDE);
    gemm_t16<2><<<dim3(S_SIDE/128, BB), blk, T16_SMEM>>>(
        wbf + WFO, ffn_out_b, tA, out, S_SIDE);
}

// round 13
// speedup vs baseline: 2.4753x; 1.0496x over previous
#include <cuda_runtime.h>
#include <cuda_fp16.h>
#include <cstdint>

#define BB 8
#define CC 128
#define TT 128
#define FF 512
#define KK 64
#define S_SIDE (TT*FF)
#define S_LAT  (TT*KK)

typedef unsigned long long u64;
typedef unsigned int u32;
typedef unsigned short u16;

// ---------------- scratch ----------------
__device__ float g_buf1[BB*CC*S_SIDE];            // attention out
__device__ float g_buf2[BB*CC*S_SIDE];            // q (fp32)
__device__ float g_buf3[BB*CC*S_SIDE];            // query_h (fp32, for skip)
__device__ float g_k  [BB*CC*S_LAT];
__device__ float g_v  [BB*CC*S_LAT];
__device__ float g_qbias[CC];                     // folded q bias

// fp16 tile buffers: per (b,tile128): 16384 u16
__device__ u16 g_tA[8*512*16384];                 // glu1 out / glu2 out
__device__ u16 g_tL[8*64*16384];                  // latent_h

// pre-converted fp16 weights
#define WLP 0
#define WK  16384
#define WV  32768
#define WQO 49152
#define WO  65536
#define WFO 81920
#define WQI 98304
#define WFI 131072
__device__ u16 g_wbf[163840];
__device__ u16 g_wq[16384];                       // folded q weights (fp16)

__device__ __forceinline__ float silu_f(float x) { return x / (1.0f + __expf(-x)); }
__device__ __forceinline__ u64 dup2(float v) {
    u64 r; asm("mov.b64 %0, {%1, %2};" : "=l"(r) : "f"(v), "f"(v)); return r;
}
__device__ __forceinline__ void fma2(u64& d, u64 a, u64 b) {
    asm("fma.rn.f32x2 %0, %1, %2, %0;" : "+l"(d) : "l"(a), "l"(b));
}
__device__ __forceinline__ float2 unpack2(u64 v) {
    float2 r; asm("mov.b64 {%0, %1}, %2;" : "=f"(r.x), "=f"(r.y) : "l"(v)); return r;
}
__device__ __forceinline__ u32 smem_u32(const void* p) {
    u32 a;
    asm("{ .reg .u64 t; cvta.to.shared.u64 t, %1; cvt.u32.u64 %0, t; }" : "=r"(a) : "l"(p));
    return a;
}

// ---------------- mma.sync helpers (fp16) ----------------
__device__ __forceinline__ void ldsm4(u32* r, u32 addr) {
    asm volatile("ldmatrix.sync.aligned.m8n8.x4.shared.b16 {%0,%1,%2,%3}, [%4];"
                 : "=r"(r[0]), "=r"(r[1]), "=r"(r[2]), "=r"(r[3]) : "r"(addr));
}
__device__ __forceinline__ void mma16816(float* d, const u32* a, const u32* b) {
    asm volatile("mma.sync.aligned.m16n8k16.row.col.f32.f16.f16.f32 "
                 "{%0,%1,%2,%3}, {%4,%5,%6,%7}, {%8,%9}, {%0,%1,%2,%3};"
                 : "+f"(d[0]), "+f"(d[1]), "+f"(d[2]), "+f"(d[3])
                 : "r"(a[0]), "r"(a[1]), "r"(a[2]), "r"(a[3]), "r"(b[0]), "r"(b[1]));
}
__device__ __forceinline__ void cpa16(u32 saddr, const void* g) {
    asm volatile("cp.async.cg.shared.global [%0], [%1], 16;" :: "r"(saddr), "l"(g));
}
#define CP_COMMIT() asm volatile("cp.async.commit_group;" ::: "memory")
#define CP_WAIT0()  asm volatile("cp.async.wait_group 0;" ::: "memory")

#define TSTR  272
#define TILE_B (128*TSTR)
#define TPH 136

// fp32x4 -> fp16x4 store into padded smem tile
__device__ __forceinline__ void cvt_store4h(char* smem, u32 base, int row, int col, float4 x) {
    __half h0 = __float2half_rn(x.x);
    __half h1 = __float2half_rn(x.y);
    __half h2 = __float2half_rn(x.z);
    __half h3 = __float2half_rn(x.w);
    u64 hv = (u64)*(u16*)&h0 | ((u64)*(u16*)&h1 << 16) | ((u64)*(u16*)&h2 << 32) | ((u64)*(u16*)&h3 << 48);
    *(u64*)(smem + base + (u32)(row * TSTR + col * 2)) = hv;
}

// stage one contiguous 128x128 u16 tile into TSTR-padded smem via cp.async
__device__ __forceinline__ void stage_tile(u32 sbase, const u16* g, int tid) {
    #pragma unroll
    for (int it = 0; it < 8; it++) {
        int idx = tid + it * 256;
        int r = idx >> 4, ch = idx & 15;
        cpa16(sbase + r * TSTR + ch * 16, g + r * 128 + ch * 8);
    }
}

// one k=128 HMMA pass; warp covers 32m x 64n
__device__ __forceinline__ void mm_pass(u32 ab, u32 bb, float (*acc)[8][4],
                                        u32 a_row, u32 a_koff, u32 b_row, u32 b_koff,
                                        int n_blk)
{
    #pragma unroll
    for (int ks = 0; ks < 8; ks++) {
        int k0 = ks * 16;
        u32 af[2][4], bf[4][4];
        #pragma unroll
        for (int i = 0; i < 2; i++)
            ldsm4(af[i], ab + (a_row + i * 16) * TSTR + (k0 + a_koff) * 2);
        #pragma unroll
        for (int j = 0; j < 4; j++)
            ldsm4(bf[j], bb + (n_blk + j * 16 + b_row) * TSTR + (k0 + b_koff) * 2);
        #pragma unroll
        for (int i = 0; i < 2; i++)
            #pragma unroll
            for (int j = 0; j < 8; j++)
                mma16816(acc[i][j], af[i], &bf[j >> 1][(j & 1) * 2]);
    }
}

// ---------------- fused weight pre-convert (gamma folded, fp16) ----------------
__global__ __launch_bounds__(256)
void convert_all(const float* __restrict__ lp_w, const float* __restrict__ k_w,
                 const float* __restrict__ v_w,  const float* __restrict__ qo_w,
                 const float* __restrict__ o_w,  const float* __restrict__ fo_w,
                 const float* __restrict__ qi_w, const float* __restrict__ fi_w,
                 const float* __restrict__ lp_g, const float* __restrict__ qn_g,
                 const float* __restrict__ ffn_g, u16* __restrict__ dst)
{
    int bid = blockIdx.x;
    const float* src; const float* gamma = nullptr; int off, n, lb;
    if (bid < 384) {
        int seg = bid >> 6; lb = bid & 63; n = 16384;
        switch (seg) {
            case 0: src = lp_w; gamma = lp_g; off = WLP; break;
            case 1: src = k_w;  off = WK;  break;
            case 2: src = v_w;  off = WV;  break;
            case 3: src = qo_w; off = WQO; break;
            case 4: src = o_w;  off = WO;  break;
            default: src = fo_w; off = WFO; break;
        }
    } else if (bid < 512) {
        lb = bid - 384; src = qi_w; gamma = qn_g; off = WQI; n = 32768;
    } else {
        lb = bid - 512; src = fi_w; gamma = ffn_g; off = WFI; n = 32768;
    }
    int idx = lb * 256 + threadIdx.x;
    if (idx >= n) return;
    float v = src[idx];
    if (gamma) v *= gamma[idx & 127];
    __half h = __float2half_rn(v);
    dst[off + idx] = *(u16*)&h;
}

// ---------------- fold q through qmlp_out ----------------
__global__ __launch_bounds__(256)
void qfold_prep(const float* __restrict__ qw, const float* __restrict__ qow,
                const float* __restrict__ qob, const float* __restrict__ qb,
                u16* __restrict__ dst, float* __restrict__ qbias)
{
    int idx = blockIdx.x * 256 + threadIdx.x;   // 0..16383
    int o = idx >> 7, c = idx & 127;
    float s = 0.f;
    #pragma unroll 4
    for (int m = 0; m < 128; m++)
        s += qw[o * 128 + m] * qow[m * 128 + c];
    __half h = __float2half_rn(s);
    dst[idx] = *(u16*)&h;
    if (c == 0) {
        float t = qb[o];
        #pragma unroll 4
        for (int m = 0; m < 128; m++)
            t += qw[o * 128 + m] * qob[m];
        qbias[o] = t;
    }
}

// ================= fp16 single-pass GEMM, tile input (2 CTAs/SM) =================
#define T16_A 0
#define T16_B TILE_B
#define T16_SMEM (2*TILE_B + 512)

// EPI: 0 none, 2 += Y
template<int EPI>
__global__ __launch_bounds__(256, 2)
void gemm_t16(const u16* __restrict__ wsc, const float* __restrict__ bias,
              const u16* __restrict__ tin, float* __restrict__ Y, int S)
{
    extern __shared__ char sm[];
    u32 sb = smem_u32(sm);
    int tid = threadIdx.x;
    int wid = tid >> 5, lane = tid & 31;
    int b  = blockIdx.y;
    int s0 = blockIdx.x * 128;
    size_t tb = ((size_t)(b * gridDim.x + blockIdx.x)) * 16384;

    stage_tile(sb + T16_A, wsc, tid);
    stage_tile(sb + T16_B, tin + tb, tid);
    CP_COMMIT();

    int m_blk = (wid & 3) * 32;
    int n_blk = (wid >> 2) * 64;
    float acc[2][8][4];
    #pragma unroll
    for (int i = 0; i < 2; i++)
        #pragma unroll
        for (int j = 0; j < 8; j++)
            #pragma unroll
            for (int q = 0; q < 4; q++) acc[i][j][q] = 0.f;

    u32 a_row = (u32)(m_blk + (lane & 15));
    u32 a_koff = (u32)((lane >> 4) << 3);
    u32 b_row = (u32)((lane & 7) + ((lane >> 4) << 3));
    u32 b_koff = (u32)(((lane >> 3) & 1) << 3);

    CP_WAIT0(); __syncthreads();
    mm_pass(sb + T16_A, sb + T16_B, acc, a_row, a_koff, b_row, b_koff, n_blk);

    #pragma unroll
    for (int i = 0; i < 2; i++) {
        #pragma unroll
        for (int j = 0; j < 8; j++) {
            int c = n_blk + j * 8 + (lane & 3) * 2;
            #pragma unroll
            for (int h = 0; h < 2; h++) {
                int o = m_blk + i * 16 + (lane >> 2) + h * 8;
                float bv = bias[o];
                float v0 = acc[i][j][h * 2 + 0] + bv;
                float v1 = acc[i][j][h * 2 + 1] + bv;
                float* yp = Y + ((size_t)b * CC + o) * S + s0 + c;
                if (EPI == 2) { v0 += yp[0]; v1 += yp[1]; }
                float2 ov; ov.x = v0; ov.y = v1;
                *(float2*)yp = ov;
            }
        }
    }
}

// ================= fp16 single-pass GEMM, fp32 input, optional fused inv-rms =================
// NORM: compute inv-rms in-kernel and scale X; ACT: silu; EPI: 0 none, 1 +scl*extra;
// OUTFMT: 0 fp32, 1 tile
template<int NORM, int ACT, int EPI, int OUTFMT>
__global__ __launch_bounds__(256, 2)
void gemm_f16in(const float* __restrict__ X, const u16* __restrict__ wsc,
                const float* __restrict__ bias, float* __restrict__ Y,
                const float* __restrict__ extra, const float* __restrict__ sc_p,
                u16* __restrict__ tout, int S)
{
    extern __shared__ char sm[];
    u32 sb = smem_u32(sm);
    float* ssq = (float*)(sm + 2 * TILE_B);
    int tid = threadIdx.x;
    int wid = tid >> 5, lane = tid & 31;
    int b  = blockIdx.y;
    int s0 = blockIdx.x * 128;
    size_t tb = ((size_t)(b * gridDim.x + blockIdx.x)) * 16384;
    const float* Xb = X + (size_t)b * CC * S;

    if (NORM && tid < 128) ssq[tid] = 0.f;
    stage_tile(sb + T16_A, wsc, tid);
    CP_COMMIT();

    float rv[4] = {1.f, 1.f, 1.f, 1.f};
    if (NORM) {
        __syncthreads();   // ssq zeroed
        float local[4] = {0.f, 0.f, 0.f, 0.f};
        #pragma unroll
        for (int i = 0; i < 16; i++) {
            int s = lane + (i & 3) * 32;
            int c0 = ((wid << 2) + (i >> 2)) * 4;
            float4 x4;
            x4.x = Xb[(size_t)(c0 + 0) * S + s0 + s];
            x4.y = Xb[(size_t)(c0 + 1) * S + s0 + s];
            x4.z = Xb[(size_t)(c0 + 2) * S + s0 + s];
            x4.w = Xb[(size_t)(c0 + 3) * S + s0 + s];
            local[i & 3] += x4.x * x4.x + x4.y * x4.y + x4.z * x4.z + x4.w * x4.w;
        }
        #pragma unroll
        for (int j = 0; j < 4; j++)
            atomicAdd(&ssq[lane + j * 32], local[j]);
        __syncthreads();
        #pragma unroll
        for (int j = 0; j < 4; j++)
            rv[j] = rsqrtf(ssq[lane + j * 32] * (1.0f / CC) + 1e-6f);
    }
    {
        #pragma unroll
        for (int i = 0; i < 16; i++) {
            int s = lane + (i & 3) * 32;
            int c0 = ((wid << 2) + (i >> 2)) * 4;
            float4 x4;
            x4.x = Xb[(size_t)(c0 + 0) * S + s0 + s];
            x4.y = Xb[(size_t)(c0 + 1) * S + s0 + s];
            x4.z = Xb[(size_t)(c0 + 2) * S + s0 + s];
            x4.w = Xb[(size_t)(c0 + 3) * S + s0 + s];
            if (NORM) {
                float r = rv[i & 3];
                x4.x *= r; x4.y *= r; x4.z *= r; x4.w *= r;
            }
            cvt_store4h(sm, T16_B, s, c0, x4);
        }
    }

    int m_blk = (wid & 3) * 32;
    int n_blk = (wid >> 2) * 64;
    float acc[2][8][4];
    #pragma unroll
    for (int i = 0; i < 2; i++)
        #pragma unroll
        for (int j = 0; j < 8; j++)
            #pragma unroll
            for (int q = 0; q < 4; q++) acc[i][j][q] = 0.f;

    u32 a_row = (u32)(m_blk + (lane & 15));
    u32 a_koff = (u32)((lane >> 4) << 3);
    u32 b_row = (u32)((lane & 7) + ((lane >> 4) << 3));
    u32 b_koff = (u32)(((lane >> 3) & 1) << 3);

    CP_WAIT0(); __syncthreads();
    mm_pass(sb + T16_A, sb + T16_B, acc, a_row, a_koff, b_row, b_koff, n_blk);

    float scl = (EPI == 1) ? *sc_p : 0.f;
    u16* trans = (u16*)(sm + T16_B);
    if (OUTFMT == 1) __syncthreads();
    #pragma unroll
    for (int i = 0; i < 2; i++) {
        #pragma unroll
        for (int j = 0; j < 8; j++) {
            int c = n_blk + j * 8 + (lane & 3) * 2;
            #pragma unroll
            for (int h = 0; h < 2; h++) {
                int o = m_blk + i * 16 + (lane >> 2) + h * 8;
                float bv = bias[o];
                float v0 = acc[i][j][h * 2 + 0] + bv;
                float v1 = acc[i][j][h * 2 + 1] + bv;
                if (ACT == 1) { v0 = silu_f(v0); v1 = silu_f(v1); }
                if (OUTFMT == 0) {
                    float* yp = Y + ((size_t)b * CC + o) * S + s0 + c;
                    float w0 = v0, w1 = v1;
                    if (EPI == 1) {
                        const float* ep = extra + ((size_t)b * CC + o) * S + s0 + c;
                        w0 += scl * ep[0]; w1 += scl * ep[1];
                    }
                    float2 ov; ov.x = w0; ov.y = w1;
                    *(float2*)yp = ov;
                } else {
                    __half q0 = __float2half_rn(v0);
                    __half q1 = __float2half_rn(v1);
                    trans[c * TPH + o] = *(u16*)&q0;
                    trans[(c + 1) * TPH + o] = *(u16*)&q1;
                }
            }
        }
    }
    if (OUTFMT == 1) {
        __syncthreads();
        u16* thi = tout + tb;
        #pragma unroll
        for (int it = 0; it < 8; it++) {
            int idx = tid + it * 256;
            int s = idx >> 4, c0 = (idx & 15) * 8;
            uint4 w = *(const uint4*)(trans + s * TPH + c0);
            *(uint4*)(thi + s * 128 + c0) = w;
        }
    }
}

// ================= fp16 single-pass GLU with fused inv-rms =================
#define GL_AA 0
#define GL_AG TILE_B
#define GL_B  (2*TILE_B)
#define GL_SMEM (3*TILE_B + 512)

__global__ __launch_bounds__(256)
void glu_f16(const float* __restrict__ X, const u16* __restrict__ wsc,
             const float* __restrict__ bias, u16* __restrict__ tout, int S)
{
    extern __shared__ char sm[];
    u32 sb = smem_u32(sm);
    float* ssq = (float*)(sm + 3 * TILE_B);
    int tid = threadIdx.x;
    int wid = tid >> 5, lane = tid & 31;
    int b  = blockIdx.y;
    int s0 = blockIdx.x * 128;
    size_t tb = ((size_t)(b * gridDim.x + blockIdx.x)) * 16384;
    const float* Xb = X + (size_t)b * CC * S;

    if (tid < 128) ssq[tid] = 0.f;
    stage_tile(sb + GL_AA, wsc, tid);
    stage_tile(sb + GL_AG, wsc + 16384, tid);
    CP_COMMIT();
    __syncthreads();   // ssq zeroed

    float local[4] = {0.f, 0.f, 0.f, 0.f};
    #pragma unroll
    for (int i = 0; i < 16; i++) {
        int s = lane + (i & 3) * 32;
        int c0 = ((wid << 2) + (i >> 2)) * 4;
        float4 x4;
        x4.x = Xb[(size_t)(c0 + 0) * S + s0 + s];
        x4.y = Xb[(size_t)(c0 + 1) * S + s0 + s];
        x4.z = Xb[(size_t)(c0 + 2) * S + s0 + s];
        x4.w = Xb[(size_t)(c0 + 3) * S + s0 + s];
        local[i & 3] += x4.x * x4.x + x4.y * x4.y + x4.z * x4.z + x4.w * x4.w;
    }
    #pragma unroll
    for (int j = 0; j < 4; j++)
        atomicAdd(&ssq[lane + j * 32], local[j]);
    __syncthreads();
    float rv[4];
    #pragma unroll
    for (int j = 0; j < 4; j++)
        rv[j] = rsqrtf(ssq[lane + j * 32] * (1.0f / CC) + 1e-6f);

    #pragma unroll
    for (int i = 0; i < 16; i++) {
        int s = lane + (i & 3) * 32;
        int c0 = ((wid << 2) + (i >> 2)) * 4;
        float4 x4;
        x4.x = Xb[(size_t)(c0 + 0) * S + s0 + s];
        x4.y = Xb[(size_t)(c0 + 1) * S + s0 + s];
        x4.z = Xb[(size_t)(c0 + 2) * S + s0 + s];
        x4.w = Xb[(size_t)(c0 + 3) * S + s0 + s];
        float r = rv[i & 3];
        x4.x *= r; x4.y *= r; x4.z *= r; x4.w *= r;
        cvt_store4h(sm, GL_B, s, c0, x4);
    }
    CP_WAIT0();
    __syncthreads();

    int m_blk = (wid & 3) * 32;
    int n_blk = (wid >> 2) * 64;
    float acca[2][8][4], accg[2][8][4];
    #pragma unroll
    for (int i = 0; i < 2; i++)
        #pragma unroll
        for (int j = 0; j < 8; j++)
            #pragma unroll
            for (int q = 0; q < 4; q++) { acca[i][j][q] = 0.f; accg[i][j][q] = 0.f; }

    u32 a_row = (u32)(m_blk + (lane & 15));
    u32 a_koff = (u32)((lane >> 4) << 3);
    u32 b_row = (u32)((lane & 7) + ((lane >> 4) << 3));
    u32 b_koff = (u32)(((lane >> 3) & 1) << 3);

    mm_pass(sb + GL_AA, sb + GL_B, acca, a_row, a_koff, b_row, b_koff, n_blk);
    mm_pass(sb + GL_AG, sb + GL_B, accg, a_row, a_koff, b_row, b_koff, n_blk);

    u16* trans = (u16*)sm;
    __syncthreads();
    #pragma unroll
    for (int i = 0; i < 2; i++) {
        #pragma unroll
        for (int j = 0; j < 8; j++) {
            int c = n_blk + j * 8 + (lane & 3) * 2;
            #pragma unroll
            for (int h = 0; h < 2; h++) {
                int o = m_blk + i * 16 + (lane >> 2) + h * 8;
                float ba = bias[o], bg = bias[CC + o];
                float v0 = (acca[i][j][h * 2 + 0] + ba) * silu_f(accg[i][j][h * 2 + 0] + bg);
                float v1 = (acca[i][j][h * 2 + 1] + ba) * silu_f(accg[i][j][h * 2 + 1] + bg);
                __half q0 = __float2half_rn(v0);
                __half q1 = __float2half_rn(v1);
                trans[c * TPH + o] = *(u16*)&q0;
                trans[(c + 1) * TPH + o] = *(u16*)&q1;
            }
        }
    }
    __syncthreads();
    {
        u16* thi = tout + tb;
        #pragma unroll
        for (int it = 0; it < 8; it++) {
            int idx = tid + it * 256;
            int s = idx >> 4, c0 = (idx & 15) * 8;
            uint4 w = *(const uint4*)(trans + s * TPH + c0);
            *(uint4*)(thi + s * 128 + c0) = w;
        }
    }
}

// ---------------- Attention (SIMT fp32, unchanged) ----------------
#define ATT_SMEM_FLOATS (128*72 + 2*64*136)
#define ATT_SMEM_BYTES  (ATT_SMEM_FLOATS * 4)

__global__ __launch_bounds__(256)
void attn_kernel(const float* __restrict__ q, const float* __restrict__ kmat,
                 const float* __restrict__ vmat, const float* __restrict__ basis,
                 const float* __restrict__ ss_p, const float* __restrict__ ps_p,
                 float* __restrict__ att)
{
    extern __shared__ float smf[];
    float* Ks  = smf;
    float* Qs  = smf + 128 * 72;
    float* Vt  = Qs;
    float* Wsm = Qs + 64 * 136;

    int fb = blockIdx.x * 128;
    int t  = blockIdx.y;
    int b  = blockIdx.z;
    int tid = threadIdx.x;
    int tx = tid & 15, ty = tid >> 4;

    const float* kb = kmat + (size_t)b * CC * S_LAT + t * KK;
    #pragma unroll
    for (int it = 0; it < 8; it++) {
        int idx = tid + it * 256;
        int c = idx >> 4, kq = idx & 15;
        float4 v = *(const float4*)(kb + (size_t)c * S_LAT + kq * 4);
        *(float4*)&Ks[c * 72 + kq * 4] = v;
    }
    const float* qb = q + (size_t)b * CC * S_SIDE + t * FF + fb;
    #pragma unroll
    for (int it = 0; it < 16; it++) {
        int idx = tid + it * 256;
        int c = idx >> 5, fq = idx & 31;
        float4 v = *(const float4*)(qb + (size_t)c * S_SIDE + fq * 4);
        *(float4*)&Qs[c * 128 + fq * 4] = v;
    }
    __syncthreads();

    u64 sc2[8][2];
    #pragma unroll
    for (int i = 0; i < 8; i++) { sc2[i][0] = 0ull; sc2[i][1] = 0ull; }

    #pragma unroll 4
    for (int c = 0; c < CC; c++) {
        u64 kp0 = *(const u64*)&Ks[c * 72 + tx * 4];
        u64 kp1 = *(const u64*)&Ks[c * 72 + tx * 4 + 2];
        float4 q0 = *(const float4*)&Qs[c * 128 + ty * 8];
        float4 q1 = *(const float4*)&Qs[c * 128 + ty * 8 + 4];
        u64 qd[8] = {dup2(q0.x),dup2(q0.y),dup2(q0.z),dup2(q0.w),
                     dup2(q1.x),dup2(q1.y),dup2(q1.z),dup2(q1.w)};
        #pragma unroll
        for (int i = 0; i < 8; i++) {
            fma2(sc2[i][0], qd[i], kp0);
            fma2(sc2[i][1], qd[i], kp1);
        }
    }
    float sc[8][4];
    #pragma unroll
    for (int i = 0; i < 8; i++) {
        float2 p0 = unpack2(sc2[i][0]);
        float2 p1 = unpack2(sc2[i][1]);
        sc[i][0] = p0.x; sc[i][1] = p0.y; sc[i][2] = p1.x; sc[i][3] = p1.y;
    }
    float ssv = *ss_p, psv = *ps_p;
    #pragma unroll
    for (int i = 0; i < 8; i++)
        #pragma unroll
        for (int j = 0; j < 4; j++)
            sc[i][j] = sc[i][j] * ssv
                     + basis[(tx * 4 + j) * FF + fb + ty * 8 + i] * psv;
    __syncthreads();

    float w[8][4];
    #pragma unroll
    for (int i = 0; i < 8; i++) {
        float m = fmaxf(fmaxf(sc[i][0], sc[i][1]), fmaxf(sc[i][2], sc[i][3]));
        #pragma unroll
        for (int off = 8; off >= 1; off >>= 1)
            m = fmaxf(m, __shfl_xor_sync(0xffffffffu, m, off));
        float e0 = __expf(sc[i][0] - m);
        float e1 = __expf(sc[i][1] - m);
        float e2 = __expf(sc[i][2] - m);
        float e3 = __expf(sc[i][3] - m);
        float s = e0 + e1 + e2 + e3;
        #pragma unroll
        for (int off = 8; off >= 1; off >>= 1)
            s += __shfl_xor_sync(0xffffffffu, s, off);
        float inv = 1.0f / s;
        w[i][0] = e0 * inv; w[i][1] = e1 * inv;
        w[i][2] = e2 * inv; w[i][3] = e3 * inv;
    }
    #pragma unroll
    for (int i = 0; i < 8; i++)
        #pragma unroll
        for (int j = 0; j < 4; j++)
            Wsm[(tx * 4 + j) * 136 + ty * 8 + i] = w[i][j];

    const float* vb = vmat + (size_t)b * CC * S_LAT + t * KK;
    #pragma unroll
    for (int it = 0; it < 8; it++) {
        int idx = tid + it * 256;
        int c = idx >> 4, kq = idx & 15;
        float4 v = *(const float4*)(vb + (size_t)c * S_LAT + kq * 4);
        Vt[(kq * 4 + 0) * 136 + c] = v.x;
        Vt[(kq * 4 + 1) * 136 + c] = v.y;
        Vt[(kq * 4 + 2) * 136 + c] = v.z;
        Vt[(kq * 4 + 3) * 136 + c] = v.w;
    }
    __syncthreads();

    u64 ac2[4][8];
    #pragma unroll
    for (int i = 0; i < 4; i++)
        #pragma unroll
        for (int j = 0; j < 8; j++) ac2[i][j] = 0ull;

    #pragma unroll 4
    for (int k = 0; k < KK; k++) {
        u64 vp[4];
        #pragma unroll
        for (int i = 0; i < 4; i++)
            vp[i] = *(const u64*)&Vt[k * 136 + ty * 8 + 2 * i];
        float4 w0 = *(const float4*)&Wsm[k * 136 + tx * 8];
        float4 w1 = *(const float4*)&Wsm[k * 136 + tx * 8 + 4];
        u64 wd[8] = {dup2(w0.x),dup2(w0.y),dup2(w0.z),dup2(w0.w),
                     dup2(w1.x),dup2(w1.y),dup2(w1.z),dup2(w1.w)};
        #pragma unroll
        for (int i = 0; i < 4; i++)
            #pragma unroll
            for (int j = 0; j < 8; j++)
                fma2(ac2[i][j], vp[i], wd[j]);
    }
    #pragma unroll
    for (int i = 0; i < 4; i++) {
        float r0[8], r1[8];
        #pragma unroll
        for (int j = 0; j < 8; j++) {
            float2 p = unpack2(ac2[i][j]);
            r0[j] = p.x; r1[j] = p.y;
        }
        #pragma unroll
        for (int half = 0; half < 2; half++) {
            int c = ty * 8 + 2 * i + half;
            float* rr = half ? r1 : r0;
            float* orow = att + (((size_t)b * CC + c) * TT + t) * FF + fb + tx * 8;
            *(float4*)(orow + 0) = make_float4(rr[0], rr[1], rr[2], rr[3]);
            *(float4*)(orow + 4) = make_float4(rr[4], rr[5], rr[6], rr[7]);
        }
    }
}

// ---------------- host ----------------
extern "C" void kernel_launch(void* const* d_in, const int* in_sizes, int n_in,
                              void* d_out, int out_size)
{
    const float* latent     = (const float*)d_in[0];
    const float* side       = (const float*)d_in[1];
    const float* basis      = (const float*)d_in[2];
    const float* lp_gamma   = (const float*)d_in[3];
    const float* lp_w       = (const float*)d_in[4];
    const float* lp_b       = (const float*)d_in[5];
    const float* qn_gamma   = (const float*)d_in[6];
    const float* qmlp_in_w  = (const float*)d_in[7];
    const float* qmlp_in_b  = (const float*)d_in[8];
    const float* qmlp_out_w = (const float*)d_in[9];
    const float* qmlp_out_b = (const float*)d_in[10];
    const float* q_w        = (const float*)d_in[11];
    const float* q_b        = (const float*)d_in[12];
    const float* k_w        = (const float*)d_in[13];
    const float* k_b        = (const float*)d_in[14];
    const float* v_w        = (const float*)d_in[15];
    const float* v_b        = (const float*)d_in[16];
    const float* o_w        = (const float*)d_in[17];
    const float* o_b        = (const float*)d_in[18];
    const float* ffn_gamma  = (const float*)d_in[19];
    const float* ffn_in_w   = (const float*)d_in[20];
    const float* ffn_in_b   = (const float*)d_in[21];
    const float* ffn_out_w  = (const float*)d_in[22];
    const float* ffn_out_b  = (const float*)d_in[23];
    const float* score_sc   = (const float*)d_in[24];
    const float* prior_sc   = (const float*)d_in[25];
    const float* qskip_sc   = (const float*)d_in[26];
    float* out = (float*)d_out;

    float *buf1, *buf2, *buf3, *kmat, *vmat, *qbias;
    u16 *tA, *tL, *wbf, *wq;
    cudaGetSymbolAddress((void**)&buf1, g_buf1);
    cudaGetSymbolAddress((void**)&buf2, g_buf2);
    cudaGetSymbolAddress((void**)&buf3, g_buf3);
    cudaGetSymbolAddress((void**)&kmat, g_k);
    cudaGetSymbolAddress((void**)&vmat, g_v);
    cudaGetSymbolAddress((void**)&qbias, g_qbias);
    cudaGetSymbolAddress((void**)&tA,   g_tA);
    cudaGetSymbolAddress((void**)&tL,   g_tL);
    cudaGetSymbolAddress((void**)&wbf,  g_wbf);
    cudaGetSymbolAddress((void**)&wq,   g_wq);

    cudaFuncSetAttribute(attn_kernel, cudaFuncAttributeMaxDynamicSharedMemorySize, ATT_SMEM_BYTES);
    cudaFuncSetAttribute(gemm_f16in<1,1,0,1>, cudaFuncAttributeMaxDynamicSharedMemorySize, T16_SMEM);
    cudaFuncSetAttribute(gemm_f16in<0,0,1,0>, cudaFuncAttributeMaxDynamicSharedMemorySize, T16_SMEM);
    cudaFuncSetAttribute(gemm_t16<0>, cudaFuncAttributeMaxDynamicSharedMemorySize, T16_SMEM);
    cudaFuncSetAttribute(gemm_t16<2>, cudaFuncAttributeMaxDynamicSharedMemorySize, T16_SMEM);
    cudaFuncSetAttribute(glu_f16, cudaFuncAttributeMaxDynamicSharedMemorySize, GL_SMEM);

    dim3 blk(256);

    // 0: fused weight pre-convert
    convert_all<<<640, blk>>>(lp_w, k_w, v_w, qmlp_out_w, o_w, ffn_out_w,
                              qmlp_in_w, ffn_in_w, lp_gamma, qn_gamma, ffn_gamma, wbf);
    // 1: fold q through qmlp_out
    qfold_prep<<<64, blk>>>(q_w, qmlp_out_w, qmlp_out_b, q_b, wq, qbias);

    // 2: glu1 (fused rms) — target of the profiled slot
    glu_f16<<<dim3(S_SIDE/128, BB), blk, GL_SMEM>>>(side, wbf + WQI, qmlp_in_b, tA, S_SIDE);

    // 3: latent_pre (fused rms, tile out)
    gemm_f16in<1,1,0,1><<<dim3(S_LAT/128, BB), blk, T16_SMEM>>>(
        latent, wbf + WLP, lp_b, nullptr, nullptr, nullptr, tL, S_LAT);

    // 4: qmlp_out -> buf3 (fp32; q is folded so no tile needed)
    gemm_t16<0><<<dim3(S_SIDE/128, BB), blk, T16_SMEM>>>(
        wbf + WQO, qmlp_out_b, tA, buf3, S_SIDE);

    // 5: q (folded weights, reads tA)
    gemm_t16<0><<<dim3(S_SIDE/128, BB), blk, T16_SMEM>>>(
        wq, qbias, tA, buf2, S_SIDE);

    // 6,7: k, v
    gemm_t16<0><<<dim3(S_LAT/128, BB), blk, T16_SMEM>>>(
        wbf + WK, k_b, tL, kmat, S_LAT);
    gemm_t16<0><<<dim3(S_LAT/128, BB), blk, T16_SMEM>>>(
        wbf + WV, v_b, tL, vmat, S_LAT);

    // 8: attention
    attn_kernel<<<dim3(FF/128, TT, BB), blk, ATT_SMEM_BYTES>>>(
        buf2, kmat, vmat, basis, score_sc, prior_sc, buf1);

    // 9: o-proj + query skip
    gemm_f16in<0,0,1,0><<<dim3(S_SIDE/128, BB), blk, T16_SMEM>>>(
        buf1, wbf + WO, o_b, out, buf3, qskip_sc, nullptr, S_SIDE);

    // 10: glu2 (fused rms on `out`)
    glu_f16<<<dim3(S_SIDE/128, BB), blk, GL_SMEM>>>(out, wbf + WFI, ffn_in_b, tA, S_SIDE);

    // 11: ffn_out (residual into out)
    gemm_t16<2><<<dim3(S_SIDE/128, BB), blk, T16_SMEM>>>(
        wbf + WFO, ffn_out_b, tA, out, S_SIDE);
}